// round 12
// baseline (speedup 1.0000x reference)
#include <cuda_runtime.h>
#include <cuda_bf16.h>
#include <cstdint>

// ---------------- problem constants ----------------
#define B_   8
#define T_   2048
#define TC_  512
#define D_   1024
#define DC_  512
#define N_   2560   // T_ + TC_
#define H_   8
#define HD_  128
#define NEGV (-1000000.0f)

// ---------------- scratch (device globals: allocation-free rule) ----------------
__device__ float g_key[(size_t)B_ * N_ * D_];
__device__ float g_v[(size_t)B_ * N_ * D_];
__device__ float g_colsum[B_ * D_];
__device__ float g_attnT[(size_t)B_ * H_ * HD_ * HD_];

__device__ __nv_bfloat16 g_xn_h[(size_t)B_ * T_ * D_];
__device__ __nv_bfloat16 g_xn_l[(size_t)B_ * T_ * D_];
__device__ __nv_bfloat16 g_cn_h[(size_t)B_ * TC_ * DC_];
__device__ __nv_bfloat16 g_cn_l[(size_t)B_ * TC_ * DC_];
__device__ __nv_bfloat16 g_q_h[(size_t)B_ * T_ * D_];
__device__ __nv_bfloat16 g_q_l[(size_t)B_ * T_ * D_];
__device__ __nv_bfloat16 g_at_h[(size_t)B_ * H_ * HD_ * HD_];
__device__ __nv_bfloat16 g_at_l[(size_t)B_ * H_ * HD_ * HD_];
__device__ __nv_bfloat16 g_y_h[(size_t)B_ * T_ * D_];
__device__ __nv_bfloat16 g_y_l[(size_t)B_ * T_ * D_];
__device__ __nv_bfloat16 g_wkx_h[D_ * D_], g_wkx_l[D_ * D_];
__device__ __nv_bfloat16 g_wvx_h[D_ * D_], g_wvx_l[D_ * D_];
__device__ __nv_bfloat16 g_wy_h[D_ * D_],  g_wy_l[D_ * D_];
__device__ __nv_bfloat16 g_wkc_h[D_ * DC_], g_wkc_l[D_ * DC_];
__device__ __nv_bfloat16 g_wvc_h[D_ * DC_], g_wvc_l[D_ * DC_];

// ---------------- small PTX helpers (plain sm_103-safe: sm_80-era ISA only) ----------------
__device__ __forceinline__ uint32_t smem_u32(const void* p) {
    uint32_t a;
    asm("{ .reg .u64 t; cvta.to.shared.u64 t, %1; cvt.u32.u64 %0, t; }" : "=r"(a) : "l"(p));
    return a;
}
#define CP_ASYNC16(sm, gp) \
    asm volatile("cp.async.cg.shared.global [%0], [%1], 16;" :: "r"(sm), "l"(gp) : "memory")
#define CP_COMMIT() asm volatile("cp.async.commit_group;" ::: "memory")
#define CP_WAIT(n)  asm volatile("cp.async.wait_group %0;" :: "n"(n) : "memory")

__device__ __forceinline__ void ldmatrix4(uint32_t* r, uint32_t addr) {
    asm volatile("ldmatrix.sync.aligned.m8n8.x4.shared.b16 {%0,%1,%2,%3}, [%4];"
                 : "=r"(r[0]), "=r"(r[1]), "=r"(r[2]), "=r"(r[3]) : "r"(addr));
}
__device__ __forceinline__ void mma16816(float* d, const uint32_t* a, uint32_t b0, uint32_t b1) {
    asm volatile("mma.sync.aligned.m16n8k16.row.col.f32.bf16.bf16.f32 "
                 "{%0,%1,%2,%3}, {%4,%5,%6,%7}, {%8,%9}, {%0,%1,%2,%3};"
                 : "+f"(d[0]), "+f"(d[1]), "+f"(d[2]), "+f"(d[3])
                 : "r"(a[0]), "r"(a[1]), "r"(a[2]), "r"(a[3]), "r"(b0), "r"(b1));
}

// ---------------- bf16 split-precision HMMA GEMM (fused hi/lo chunks) ----------------
//  C = (Ah+Al)(M,K) * (Wh+Wl)(N,K)^T  =  Ah*Wh + Ah*Wl + Al*Wh   (fp32 accum)
//  CTA tile 128x128, warp tile 64x32, K-chunk 32 fp32-K.
//  smem row (128B) packs hi (16B groups 0-3) and lo (groups 4-7) of the SAME 32-k
//  slice, XOR-by-(row&7) swizzle => conflict-free ldmatrix, single K-pass,
//  B-hi fragments reused across hh+lh, A-hi across hh+hl (1.5x fewer LDSM + gmem).
//  Batch: z -> zo = z / zInner, zi = z % zInner; offsets aO*zo + aI*zi etc.
//  epilogue modes: 0: +bias ; 1: +bias + (1-mask[m])*NEG ; 2: (+bias)*mask[m] ;
//                  3: write bf16 hi/lo pair to Chi/Clo (no bias/mask)
#define HG_STAGES      3
#define HG_STAGE_BYTES 32768          // A 16KB + B 16KB (hi+lo packed)
#define HG_SMEM_BYTES  (1024 + HG_STAGES * HG_STAGE_BYTES)

__device__ __forceinline__ void hg_issue_chunk(
    const __nv_bfloat16* Ah, const __nv_bfloat16* Al,
    const __nv_bfloat16* Wh, const __nv_bfloat16* Wl,
    int m0, int n0, int lda, int ldw, int k0,
    uint32_t sA, uint32_t sB, int tid)
{
    const int g  = tid & 7;            // 16B group within 128B row
    const int go = (g & 3) * 8;        // element offset within the 32-k slice
    const bool lo = (g & 4) != 0;
    const __nv_bfloat16* Asel = lo ? Al : Ah;
    const __nv_bfloat16* Wsel = lo ? Wl : Wh;
#pragma unroll
    for (int i = 0; i < 4; ++i) {
        const int row = (tid + i * 256) >> 3;          // 0..127
        const uint32_t sw = row * 128 + (((uint32_t)(g ^ (row & 7))) << 4);
        CP_ASYNC16(sA + sw, Asel + (size_t)(m0 + row) * lda + k0 + go);
    }
#pragma unroll
    for (int i = 0; i < 4; ++i) {
        const int row = (tid + i * 256) >> 3;
        const uint32_t sw = row * 128 + (((uint32_t)(g ^ (row & 7))) << 4);
        CP_ASYNC16(sB + sw, Wsel + (size_t)(n0 + row) * ldw + k0 + go);
    }
    CP_COMMIT();
}

__global__ void __launch_bounds__(256, 2) hgemm(
    const __nv_bfloat16* __restrict__ Ah, const __nv_bfloat16* __restrict__ Al,
    const __nv_bfloat16* __restrict__ Wh, const __nv_bfloat16* __restrict__ Wl,
    float* __restrict__ C,
    __nv_bfloat16* __restrict__ Chi, __nv_bfloat16* __restrict__ Clo,
    int lda, int ldw, int ldc, int Kd,
    long aO, long aI, long wO, long wI, long cO, long cI, int zInner,
    const float* __restrict__ bias,
    const float* __restrict__ mask, long maskStride, int mode)
{
    extern __shared__ char smraw[];
    const uint32_t sbase = (smem_u32(smraw) + 1023u) & ~1023u;

    const int tid = threadIdx.x;
    const int w = tid >> 5, lane = tid & 31;
    const long z = blockIdx.z;
    const long zo = z / zInner, zi = z % zInner;
    const long aoff = zo * aO + zi * aI;
    const long woff = zo * wO + zi * wI;
    const long coff = zo * cO + zi * cI;
    Ah += aoff; Al += aoff;
    Wh += woff; Wl += woff;
    if (C)   C   += coff;
    if (Chi) { Chi += coff; Clo += coff; }
    const float* mk = mask ? (mask + zo * maskStride) : nullptr;
    const int m0 = blockIdx.y * 128, n0 = blockIdx.x * 128;

    const int wm = (w >> 2) * 64;     // warp row base within tile (0 or 64)
    const int wn = (w & 3) * 32;      // warp col base within tile

    float acc[4][4][4];
#pragma unroll
    for (int a = 0; a < 4; ++a)
#pragma unroll
        for (int b = 0; b < 4; ++b)
#pragma unroll
            for (int c = 0; c < 4; ++c) acc[a][b][c] = 0.f;

    const int nchunks = Kd >> 5;      // 32 fp32-K per chunk

    // prologue: issue chunks 0 and 1 into slots 0, 1 (slot 2 stays free)
    hg_issue_chunk(Ah, Al, Wh, Wl, m0, n0, lda, ldw, 0,
                   sbase, sbase + 16384, tid);
    hg_issue_chunk(Ah, Al, Wh, Wl, m0, n0, lda, ldw, 32,
                   sbase + HG_STAGE_BYTES, sbase + HG_STAGE_BYTES + 16384, tid);

    // per-lane ldmatrix row fragments
    const int rl = lane & 15;         // row within 16-row group
    const int kh = lane >> 4;         // 0/1 -> k-subgroup select

    for (int c = 0; c < nchunks; ++c) {
        CP_WAIT(1);                   // chunk c's group retired (exactly 1 commit/iter)
        __syncthreads();              // orders last iter's reads of slot (c+2)%3

        if (c + 2 < nchunks) {
            const uint32_t slot = sbase + (uint32_t)((c + 2) % HG_STAGES) * HG_STAGE_BYTES;
            hg_issue_chunk(Ah, Al, Wh, Wl, m0, n0, lda, ldw, (c + 2) << 5,
                           slot, slot + 16384, tid);
        } else {
            CP_COMMIT();              // empty group keeps wait_group accounting exact
        }

        const uint32_t sA = sbase + (uint32_t)(c % HG_STAGES) * HG_STAGE_BYTES;
        const uint32_t sB = sA + 16384;

#pragma unroll
        for (int ks = 0; ks < 2; ++ks) {
            const int gh = 2 * ks + kh;   // hi group (0..3)
            const int gl = gh + 4;        // lo group (4..7)

            // B fragments (hi + lo) — reused across both A variants
            uint32_t brh[2][4], brl[2][4];
#pragma unroll
            for (int tp = 0; tp < 2; ++tp) {
                const int row = wn + tp * 16 + rl;
                const uint32_t rb = sB + row * 128;
                const uint32_t x = (row & 7) << 4;
                ldmatrix4(brh[tp], rb + (((uint32_t)gh << 4) ^ x));
                ldmatrix4(brl[tp], rb + (((uint32_t)gl << 4) ^ x));
            }
            // A-hi fragments: hh + hl products
            uint32_t ar[4][4];
#pragma unroll
            for (int tm = 0; tm < 4; ++tm) {
                const int row = wm + tm * 16 + rl;
                ldmatrix4(ar[tm], sA + row * 128 + ((((uint32_t)gh << 4)) ^ ((row & 7) << 4)));
            }
#pragma unroll
            for (int tm = 0; tm < 4; ++tm)
#pragma unroll
                for (int tn = 0; tn < 4; ++tn) {
                    const int u = tn & 1;
                    mma16816(acc[tm][tn], ar[tm], brh[tn >> 1][u], brh[tn >> 1][u + 2]);
                    mma16816(acc[tm][tn], ar[tm], brl[tn >> 1][u], brl[tn >> 1][u + 2]);
                }
            // A-lo fragments: lh product (overwrites ar)
#pragma unroll
            for (int tm = 0; tm < 4; ++tm) {
                const int row = wm + tm * 16 + rl;
                ldmatrix4(ar[tm], sA + row * 128 + ((((uint32_t)gl << 4)) ^ ((row & 7) << 4)));
            }
#pragma unroll
            for (int tm = 0; tm < 4; ++tm)
#pragma unroll
                for (int tn = 0; tn < 4; ++tn) {
                    const int u = tn & 1;
                    mma16816(acc[tm][tn], ar[tm], brh[tn >> 1][u], brh[tn >> 1][u + 2]);
                }
        }
    }

    // ---------------- epilogue ----------------
    const int r0l = lane >> 2;        // 0..7
    const int c0l = (lane & 3) * 2;
    if (mode == 3) {
        // write bf16 hi/lo pair
#pragma unroll
        for (int tm = 0; tm < 4; ++tm) {
            const int row0 = m0 + wm + tm * 16 + r0l;
            const int row1 = row0 + 8;
            __nv_bfloat16* h0 = Chi + (size_t)row0 * ldc;
            __nv_bfloat16* h1 = Chi + (size_t)row1 * ldc;
            __nv_bfloat16* l0 = Clo + (size_t)row0 * ldc;
            __nv_bfloat16* l1 = Clo + (size_t)row1 * ldc;
#pragma unroll
            for (int tn = 0; tn < 4; ++tn) {
                const int col = n0 + wn + tn * 8 + c0l;
                const float d0 = acc[tm][tn][0], d1 = acc[tm][tn][1];
                const float d2 = acc[tm][tn][2], d3 = acc[tm][tn][3];
                __nv_bfloat16 a0 = __float2bfloat16(d0), a1 = __float2bfloat16(d1);
                __nv_bfloat16 a2 = __float2bfloat16(d2), a3 = __float2bfloat16(d3);
                *(__nv_bfloat162*)(h0 + col) = __halves2bfloat162(a0, a1);
                *(__nv_bfloat162*)(h1 + col) = __halves2bfloat162(a2, a3);
                *(__nv_bfloat162*)(l0 + col) = __halves2bfloat162(
                    __float2bfloat16(d0 - __bfloat162float(a0)),
                    __float2bfloat16(d1 - __bfloat162float(a1)));
                *(__nv_bfloat162*)(l1 + col) = __halves2bfloat162(
                    __float2bfloat16(d2 - __bfloat162float(a2)),
                    __float2bfloat16(d3 - __bfloat162float(a3)));
            }
        }
        return;
    }
#pragma unroll
    for (int tm = 0; tm < 4; ++tm) {
        const int row0 = m0 + wm + tm * 16 + r0l;
        const int row1 = row0 + 8;
        float mk0 = 0.f, mk1 = 0.f;
        if (mk) { mk0 = mk[row0]; mk1 = mk[row1]; }
        float* cr0 = C + (size_t)row0 * ldc;
        float* cr1 = C + (size_t)row1 * ldc;
#pragma unroll
        for (int tn = 0; tn < 4; ++tn) {
            const int col = n0 + wn + tn * 8 + c0l;
            float d0 = acc[tm][tn][0], d1 = acc[tm][tn][1];
            float d2 = acc[tm][tn][2], d3 = acc[tm][tn][3];
            if (bias) {
                const float b0 = bias[col], b1 = bias[col + 1];
                d0 += b0; d1 += b1; d2 += b0; d3 += b1;
            }
            if (mode == 1) {
                const float p0 = (1.f - mk0) * NEGV, p1 = (1.f - mk1) * NEGV;
                d0 += p0; d1 += p0; d2 += p1; d3 += p1;
            } else if (mode == 2) {
                d0 *= mk0; d1 *= mk0; d2 *= mk1; d3 *= mk1;
            }
            float2 s0; s0.x = d0; s0.y = d1;
            float2 s1; s1.x = d2; s1.y = d3;
            *(float2*)(cr0 + col) = s0;
            *(float2*)(cr1 + col) = s1;
        }
    }
}

// ---------------- layernorm -> bf16 hi/lo ----------------
template <int DLEN>
__global__ void __launch_bounds__(256) ln_hilo(const float* __restrict__ x,
                                               const float* __restrict__ gam,
                                               const float* __restrict__ bet,
                                               __nv_bfloat16* __restrict__ hi,
                                               __nv_bfloat16* __restrict__ lo)
{
    constexpr int PER = DLEN / 256;
    const size_t row = blockIdx.x;
    const float* xr = x + row * DLEN;
    float v[PER];
    float s = 0.f, sq = 0.f;
#pragma unroll
    for (int i = 0; i < PER; i++) {
        v[i] = xr[threadIdx.x + i * 256];
        s += v[i]; sq += v[i] * v[i];
    }
#pragma unroll
    for (int o = 16; o > 0; o >>= 1) {
        s  += __shfl_xor_sync(0xffffffffu, s, o);
        sq += __shfl_xor_sync(0xffffffffu, sq, o);
    }
    __shared__ float rs[8], rq[8];
    int w = threadIdx.x >> 5, l = threadIdx.x & 31;
    if (l == 0) { rs[w] = s; rq[w] = sq; }
    __syncthreads();
    float ts = 0.f, tq = 0.f;
#pragma unroll
    for (int i = 0; i < 8; i++) { ts += rs[i]; tq += rq[i]; }
    const float mean = ts / (float)DLEN;
    const float var = tq / (float)DLEN - mean * mean;
    const float rstd = rsqrtf(var + 1e-5f);
#pragma unroll
    for (int i = 0; i < PER; i++) {
        int c = threadIdx.x + i * 256;
        float o = (v[i] - mean) * rstd * gam[c] + bet[c];
        __nv_bfloat16 h = __float2bfloat16(o);
        hi[row * DLEN + c] = h;
        lo[row * DLEN + c] = __float2bfloat16(o - __bfloat162float(h));
    }
}

// ---------------- fp32 -> bf16 hi/lo convert ----------------
__global__ void __launch_bounds__(256) cvt_hilo(const float4* __restrict__ s,
                                                __nv_bfloat162* __restrict__ hi,
                                                __nv_bfloat162* __restrict__ lo, int n4)
{
    int i = blockIdx.x * blockDim.x + threadIdx.x;
    if (i < n4) {
        float4 v = s[i];
        __nv_bfloat16 h0 = __float2bfloat16(v.x), h1 = __float2bfloat16(v.y);
        __nv_bfloat16 h2 = __float2bfloat16(v.z), h3 = __float2bfloat16(v.w);
        hi[2 * i]     = __halves2bfloat162(h0, h1);
        hi[2 * i + 1] = __halves2bfloat162(h2, h3);
        lo[2 * i]     = __halves2bfloat162(__float2bfloat16(v.x - __bfloat162float(h0)),
                                           __float2bfloat16(v.y - __bfloat162float(h1)));
        lo[2 * i + 1] = __halves2bfloat162(__float2bfloat16(v.z - __bfloat162float(h2)),
                                           __float2bfloat16(v.w - __bfloat162float(h3)));
    }
}

// ---------------- q softmax over last dim (128) -> bf16 hi/lo ----------------
__global__ void __launch_bounds__(256) qsoftmax_kernel(const float* __restrict__ query,
                                                       __nv_bfloat16* __restrict__ qh,
                                                       __nv_bfloat16* __restrict__ ql)
{
    const size_t row = blockIdx.x;
    int w = threadIdx.x >> 5, l = threadIdx.x & 31;
    const float* src = query + row * D_ + (size_t)w * HD_;
    float4 v = *(const float4*)&src[l * 4];
    float m = fmaxf(fmaxf(v.x, v.y), fmaxf(v.z, v.w));
#pragma unroll
    for (int o = 16; o > 0; o >>= 1) m = fmaxf(m, __shfl_xor_sync(0xffffffffu, m, o));
    float e0 = expf(v.x - m), e1 = expf(v.y - m), e2 = expf(v.z - m), e3 = expf(v.w - m);
    float s = e0 + e1 + e2 + e3;
#pragma unroll
    for (int o = 16; o > 0; o >>= 1) s += __shfl_xor_sync(0xffffffffu, s, o);
    float inv = 1.0f / s;
    float q0 = e0 * inv, q1 = e1 * inv, q2 = e2 * inv, q3 = e3 * inv;
    __nv_bfloat16 h0 = __float2bfloat16(q0), h1 = __float2bfloat16(q1);
    __nv_bfloat16 h2 = __float2bfloat16(q2), h3 = __float2bfloat16(q3);
    const size_t off = row * D_ + (size_t)w * HD_ + l * 4;
    *(__nv_bfloat162*)(qh + off)     = __halves2bfloat162(h0, h1);
    *(__nv_bfloat162*)(qh + off + 2) = __halves2bfloat162(h2, h3);
    *(__nv_bfloat162*)(ql + off)     = __halves2bfloat162(
        __float2bfloat16(q0 - __bfloat162float(h0)),
        __float2bfloat16(q1 - __bfloat162float(h1)));
    *(__nv_bfloat162*)(ql + off + 2) = __halves2bfloat162(
        __float2bfloat16(q2 - __bfloat162float(h2)),
        __float2bfloat16(q3 - __bfloat162float(h3)));
}

// ---------------- key softmax over n ----------------
__global__ void __launch_bounds__(256) ksoftmax_kernel(float* __restrict__ key,
                                                       float* __restrict__ colsum)
{
    const int b = blockIdx.y;
    const int c0 = blockIdx.x * 64;
    const int idx = threadIdx.x & 63;
    const int r = threadIdx.x >> 6;
    float* base = key + (size_t)b * N_ * D_ + c0 + idx;
    float m = -3.0e38f;
    for (int n = r; n < N_; n += 4) m = fmaxf(m, base[(size_t)n * D_]);
    __shared__ float red[4][64];
    red[r][idx] = m;
    __syncthreads();
    m = fmaxf(fmaxf(red[0][idx], red[1][idx]), fmaxf(red[2][idx], red[3][idx]));
    __syncthreads();
    float s = 0.f;
    for (int n = r; n < N_; n += 4) {
        float e = expf(base[(size_t)n * D_] - m);
        base[(size_t)n * D_] = e;
        s += e;
    }
    red[r][idx] = s;
    __syncthreads();
    if (r == 0)
        colsum[b * D_ + c0 + idx] = red[0][idx] + red[1][idx] + red[2][idx] + red[3][idx];
}

__global__ void zero_kernel(float* __restrict__ p, int n)
{
    int i = blockIdx.x * blockDim.x + threadIdx.x;
    if (i < n) p[i] = 0.f;
}

// ---------------- fp32 FFMA2 micro-kernel (for attn) ----------------
__device__ __forceinline__ void micro8x8(const float (*As)[128], const float (*Bs)[128],
                                         int m_base, int n_base,
                                         unsigned long long acc[8][4])
{
#pragma unroll
    for (int kk = 0; kk < 8; kk++) {
        float4 a0 = *(const float4*)&As[kk][m_base];
        float4 a1 = *(const float4*)&As[kk][m_base + 4];
        float am[8] = {a0.x, a0.y, a0.z, a0.w, a1.x, a1.y, a1.z, a1.w};
        union { float4 f[2]; unsigned long long u[4]; } bb;
        bb.f[0] = *(const float4*)&Bs[kk][n_base];
        bb.f[1] = *(const float4*)&Bs[kk][n_base + 4];
#pragma unroll
        for (int i = 0; i < 8; i++) {
            unsigned long long aa;
            unsigned int ar = __float_as_uint(am[i]);
            asm("mov.b64 %0, {%1, %1};" : "=l"(aa) : "r"(ar));
#pragma unroll
            for (int j = 0; j < 4; j++)
                asm("fma.rn.f32x2 %0, %1, %2, %0;"
                    : "+l"(acc[i][j]) : "l"(aa), "l"(bb.u[j]));
        }
    }
}

// ---------------- attn: attnT[b,h,l,d] = (1/colsum) * sum_n k*v ----------------
__global__ void __launch_bounds__(256) attn_kernel(const float* __restrict__ key,
                                                   const float* __restrict__ v,
                                                   const float* __restrict__ colsum,
                                                   float* __restrict__ attnT)
{
    __shared__ float As[8][128];
    __shared__ float Bs[8][128];
    const int tid = threadIdx.x;
    const int split = blockIdx.x, h = blockIdx.y, b = blockIdx.z;
    const int n0 = split * 256;
    const float* kg = key + (size_t)b * N_ * D_ + (size_t)h * HD_;
    const float* vg = v   + (size_t)b * N_ * D_ + (size_t)h * HD_;
    const int lrow = tid >> 5;
    const int lc = (tid & 31) * 4;

    unsigned long long acc[8][4];
#pragma unroll
    for (int i = 0; i < 8; i++)
#pragma unroll
        for (int j = 0; j < 4; j++) acc[i][j] = 0ull;

    const int m_base = (tid >> 4) * 8, n_base = (tid & 15) * 8;

    float4 av = *(const float4*)&kg[(size_t)(n0 + lrow) * D_ + lc];
    float4 wv = *(const float4*)&vg[(size_t)(n0 + lrow) * D_ + lc];
    for (int nn = 0; nn < 256; nn += 8) {
        *(float4*)&As[lrow][lc] = av;
        *(float4*)&Bs[lrow][lc] = wv;
        __syncthreads();
        if (nn + 8 < 256) {
            av = *(const float4*)&kg[(size_t)(n0 + nn + 8 + lrow) * D_ + lc];
            wv = *(const float4*)&vg[(size_t)(n0 + nn + 8 + lrow) * D_ + lc];
        }
        micro8x8(As, Bs, m_base, n_base, acc);
        __syncthreads();
    }

    float* outb = attnT + ((size_t)(b * H_ + h)) * HD_ * HD_;
#pragma unroll
    for (int i = 0; i < 8; i++) {
        const int dd = m_base + i;
        const float inv = 1.0f / colsum[b * D_ + h * HD_ + dd];
#pragma unroll
        for (int j = 0; j < 4; j++) {
            unsigned int u0, u1;
            asm("mov.b64 {%0, %1}, %2;" : "=r"(u0), "=r"(u1) : "l"(acc[i][j]));
            const int ll = n_base + 2 * j;
            atomicAdd(&outb[(size_t)ll * HD_ + dd], __uint_as_float(u0) * inv);
            atomicAdd(&outb[(size_t)(ll + 1) * HD_ + dd], __uint_as_float(u1) * inv);
        }
    }
}

// ---------------- host launch ----------------
extern "C" void kernel_launch(void* const* d_in, const int* in_sizes, int n_in,
                              void* d_out, int out_size)
{
    const float* query     = (const float*)d_in[0];
    const float* x         = (const float*)d_in[1];
    const float* cond_emb  = (const float*)d_in[2];
    const float* src_mask  = (const float*)d_in[3];
    const float* cond_mask = (const float*)d_in[4];
    const float* nxg = (const float*)d_in[5];
    const float* nxb = (const float*)d_in[6];
    const float* ncg = (const float*)d_in[7];
    const float* ncb = (const float*)d_in[8];
    const float* W_kc = (const float*)d_in[9];
    const float* b_kc = (const float*)d_in[10];
    const float* W_vc = (const float*)d_in[11];
    const float* b_vc = (const float*)d_in[12];
    const float* W_kx = (const float*)d_in[13];
    const float* b_kx = (const float*)d_in[14];
    const float* W_vx = (const float*)d_in[15];
    const float* b_vx = (const float*)d_in[16];
    const float* W_y  = (const float*)d_in[17];
    const float* b_y  = (const float*)d_in[18];
    float* out = (float*)d_out;

    float *keyb, *vb, *cs, *attnT;
    __nv_bfloat16 *xnh, *xnl, *cnh, *cnl, *qh, *ql, *ath, *atl, *yh, *yl;
    __nv_bfloat16 *wkxh, *wkxl, *wvxh, *wvxl, *wyh, *wyl, *wkch, *wkcl, *wvch, *wvcl;
    cudaGetSymbolAddress((void**)&keyb, g_key);
    cudaGetSymbolAddress((void**)&vb, g_v);
    cudaGetSymbolAddress((void**)&cs, g_colsum);
    cudaGetSymbolAddress((void**)&attnT, g_attnT);
    cudaGetSymbolAddress((void**)&xnh, g_xn_h); cudaGetSymbolAddress((void**)&xnl, g_xn_l);
    cudaGetSymbolAddress((void**)&cnh, g_cn_h); cudaGetSymbolAddress((void**)&cnl, g_cn_l);
    cudaGetSymbolAddress((void**)&qh, g_q_h);   cudaGetSymbolAddress((void**)&ql, g_q_l);
    cudaGetSymbolAddress((void**)&ath, g_at_h); cudaGetSymbolAddress((void**)&atl, g_at_l);
    cudaGetSymbolAddress((void**)&yh, g_y_h);   cudaGetSymbolAddress((void**)&yl, g_y_l);
    cudaGetSymbolAddress((void**)&wkxh, g_wkx_h); cudaGetSymbolAddress((void**)&wkxl, g_wkx_l);
    cudaGetSymbolAddress((void**)&wvxh, g_wvx_h); cudaGetSymbolAddress((void**)&wvxl, g_wvx_l);
    cudaGetSymbolAddress((void**)&wyh, g_wy_h);   cudaGetSymbolAddress((void**)&wyl, g_wy_l);
    cudaGetSymbolAddress((void**)&wkch, g_wkc_h); cudaGetSymbolAddress((void**)&wkcl, g_wkc_l);
    cudaGetSymbolAddress((void**)&wvch, g_wvc_h); cudaGetSymbolAddress((void**)&wvcl, g_wvc_l);

    cudaFuncSetAttribute(hgemm, cudaFuncAttributeMaxDynamicSharedMemorySize, HG_SMEM_BYTES);

    // launches 0-3: ln, ln, qsoftmax, cvt W_kx  (aiming launch idx 4 = big hgemm
    // so ncu's -s 5 sample, offset by ~1 hidden harness launch, lands on it)
    ln_hilo<D_><<<B_ * T_, 256>>>(x, nxg, nxb, xnh, xnl);
    ln_hilo<DC_><<<B_ * TC_, 256>>>(cond_emb, ncg, ncb, cnh, cnl);
    qsoftmax_kernel<<<B_ * T_, 256>>>(query, qh, ql);
    {
        int n4 = (D_ * D_) / 4;
        cvt_hilo<<<(n4 + 255) / 256, 256>>>((const float4*)W_kx, (__nv_bfloat162*)wkxh, (__nv_bfloat162*)wkxl, n4);
    }

    // launch 4: k_x projection (profiling target)
    hgemm<<<dim3(D_ / 128, T_ / 128, B_), 256, HG_SMEM_BYTES>>>(
        xnh, xnl, wkxh, wkxl, keyb + (size_t)TC_ * D_, nullptr, nullptr,
        D_, D_, D_, D_,
        (long)T_ * D_, 0, 0, 0, (long)N_ * D_, 0, 1,
        b_kx, src_mask, (long)T_, 1);

    {
        int n4 = (D_ * D_) / 4;
        cvt_hilo<<<(n4 + 255) / 256, 256>>>((const float4*)W_vx, (__nv_bfloat162*)wvxh, (__nv_bfloat162*)wvxl, n4);
        cvt_hilo<<<(n4 + 255) / 256, 256>>>((const float4*)W_y, (__nv_bfloat162*)wyh, (__nv_bfloat162*)wyl, n4);
        int n4c = (D_ * DC_) / 4;
        cvt_hilo<<<(n4c + 255) / 256, 256>>>((const float4*)W_kc, (__nv_bfloat162*)wkch, (__nv_bfloat162*)wkcl, n4c);
        cvt_hilo<<<(n4c + 255) / 256, 256>>>((const float4*)W_vc, (__nv_bfloat162*)wvch, (__nv_bfloat162*)wvcl, n4c);
    }

    hgemm<<<dim3(D_ / 128, T_ / 128, B_), 256, HG_SMEM_BYTES>>>(
        xnh, xnl, wvxh, wvxl, vb + (size_t)TC_ * D_, nullptr, nullptr,
        D_, D_, D_, D_,
        (long)T_ * D_, 0, 0, 0, (long)N_ * D_, 0, 1,
        b_vx, src_mask, (long)T_, 2);
    hgemm<<<dim3(D_ / 128, TC_ / 128, B_), 256, HG_SMEM_BYTES>>>(
        cnh, cnl, wkch, wkcl, keyb, nullptr, nullptr,
        DC_, DC_, D_, DC_,
        (long)TC_ * DC_, 0, 0, 0, (long)N_ * D_, 0, 1,
        b_kc, cond_mask, (long)TC_, 1);
    hgemm<<<dim3(D_ / 128, TC_ / 128, B_), 256, HG_SMEM_BYTES>>>(
        cnh, cnl, wvch, wvcl, vb, nullptr, nullptr,
        DC_, DC_, D_, DC_,
        (long)TC_ * DC_, 0, 0, 0, (long)N_ * D_, 0, 1,
        b_vc, cond_mask, (long)TC_, 2);

    // softmax over sequence axis (exp in place + column sums)
    ksoftmax_kernel<<<dim3(D_ / 64, B_), 256>>>(keyb, cs);

    // attn = normalized k^T v (fp32, split-K + atomics)
    zero_kernel<<<(B_ * H_ * HD_ * HD_ + 255) / 256, 256>>>(attnT, B_ * H_ * HD_ * HD_);
    attn_kernel<<<dim3(10, H_, B_), 256>>>(keyb, vb, cs, attnT);

    // attnT -> bf16 hi/lo (4 MB, tiny)
    {
        int n4 = (B_ * H_ * HD_ * HD_) / 4;
        cvt_hilo<<<(n4 + 255) / 256, 256>>>((const float4*)attnT, (__nv_bfloat162*)ath, (__nv_bfloat162*)atl, n4);
    }

    // y = q @ attn on tensor cores, batched over z = b*H + h; writes bf16 hi/lo directly
    hgemm<<<dim3(1, T_ / 128, B_ * H_), 256, HG_SMEM_BYTES>>>(
        qh, ql, ath, atl, nullptr, yh, yl,
        D_, HD_, D_, HD_,
        (long)T_ * D_, (long)HD_,                 // A: zo=b -> +T*D, zi=h -> +HD
        (long)H_ * HD_ * HD_, (long)HD_ * HD_,    // W: zo=b, zi=h
        (long)T_ * D_, (long)HD_,                 // C: zo=b, zi=h
        H_, nullptr, nullptr, 0, 3);

    // out = y @ W_y^T + b_y on tensor cores
    hgemm<<<dim3(D_ / 128, (B_ * T_) / 128, 1), 256, HG_SMEM_BYTES>>>(
        yh, yl, wyh, wyl, out, nullptr, nullptr,
        D_, D_, D_, D_,
        0, 0, 0, 0, 0, 0, 1,
        b_y, nullptr, 0, 0);
}

// round 13
// speedup vs baseline: 1.4795x; 1.4795x over previous
#include <cuda_runtime.h>
#include <cuda_bf16.h>
#include <cstdint>

// ---------------- problem constants ----------------
#define B_   8
#define T_   2048
#define TC_  512
#define D_   1024
#define DC_  512
#define N_   2560   // T_ + TC_
#define H_   8
#define HD_  128
#define NEGV (-1000000.0f)

// ---------------- scratch (device globals: allocation-free rule) ----------------
__device__ float g_key[(size_t)B_ * N_ * D_];
__device__ float g_v[(size_t)B_ * N_ * D_];
__device__ float g_colsum[B_ * D_];
__device__ float g_attnT[(size_t)B_ * H_ * HD_ * HD_];

__device__ __nv_bfloat16 g_xn_h[(size_t)B_ * T_ * D_];
__device__ __nv_bfloat16 g_xn_l[(size_t)B_ * T_ * D_];
__device__ __nv_bfloat16 g_cn_h[(size_t)B_ * TC_ * DC_];
__device__ __nv_bfloat16 g_cn_l[(size_t)B_ * TC_ * DC_];
__device__ __nv_bfloat16 g_q_h[(size_t)B_ * T_ * D_];
__device__ __nv_bfloat16 g_q_l[(size_t)B_ * T_ * D_];
__device__ __nv_bfloat16 g_at_h[(size_t)B_ * H_ * HD_ * HD_];
__device__ __nv_bfloat16 g_at_l[(size_t)B_ * H_ * HD_ * HD_];
__device__ __nv_bfloat16 g_y_h[(size_t)B_ * T_ * D_];
__device__ __nv_bfloat16 g_y_l[(size_t)B_ * T_ * D_];
__device__ __nv_bfloat16 g_wkx_h[D_ * D_], g_wkx_l[D_ * D_];
__device__ __nv_bfloat16 g_wvx_h[D_ * D_], g_wvx_l[D_ * D_];
__device__ __nv_bfloat16 g_wy_h[D_ * D_],  g_wy_l[D_ * D_];
__device__ __nv_bfloat16 g_wkc_h[D_ * DC_], g_wkc_l[D_ * DC_];
__device__ __nv_bfloat16 g_wvc_h[D_ * DC_], g_wvc_l[D_ * DC_];

// ---------------- small PTX helpers (plain sm_103-safe: sm_80-era ISA only) ----------------
__device__ __forceinline__ uint32_t smem_u32(const void* p) {
    uint32_t a;
    asm("{ .reg .u64 t; cvta.to.shared.u64 t, %1; cvt.u32.u64 %0, t; }" : "=r"(a) : "l"(p));
    return a;
}
#define CP_ASYNC16(sm, gp) \
    asm volatile("cp.async.cg.shared.global [%0], [%1], 16;" :: "r"(sm), "l"(gp) : "memory")
#define CP_COMMIT() asm volatile("cp.async.commit_group;" ::: "memory")
#define CP_WAIT(n)  asm volatile("cp.async.wait_group %0;" :: "n"(n) : "memory")

__device__ __forceinline__ void ldmatrix4(uint32_t* r, uint32_t addr) {
    asm volatile("ldmatrix.sync.aligned.m8n8.x4.shared.b16 {%0,%1,%2,%3}, [%4];"
                 : "=r"(r[0]), "=r"(r[1]), "=r"(r[2]), "=r"(r[3]) : "r"(addr));
}
__device__ __forceinline__ void mma16816(float* d, const uint32_t* a, uint32_t b0, uint32_t b1) {
    asm volatile("mma.sync.aligned.m16n8k16.row.col.f32.bf16.bf16.f32 "
                 "{%0,%1,%2,%3}, {%4,%5,%6,%7}, {%8,%9}, {%0,%1,%2,%3};"
                 : "+f"(d[0]), "+f"(d[1]), "+f"(d[2]), "+f"(d[3])
                 : "r"(a[0]), "r"(a[1]), "r"(a[2]), "r"(a[3]), "r"(b0), "r"(b1));
}

// ---------------- bf16 split-precision HMMA GEMM (R11 version — known good) ----------------
//  C = (Ah+Al)(M,K) * (Wh+Wl)(N,K)^T   via 3 bf16 passes (hh, hl, lh), fp32 accum.
//  CTA tile 128x128, warp tile 64x32, K-chunk 64, 3-stage cp.async multistage.
//  Batch: z -> zo = z / zInner, zi = z % zInner; offsets aO*zo + aI*zi etc.
//  epilogue modes: 0: +bias ; 1: +bias + (1-mask[m])*NEG ; 2: (+bias)*mask[m] ;
//                  3: write bf16 hi/lo pair to Chi/Clo (no bias/mask)
#define HG_STAGES      3
#define HG_STAGE_BYTES 32768          // A 16KB + B 16KB
#define HG_SMEM_BYTES  (1024 + HG_STAGES * HG_STAGE_BYTES)

__device__ __forceinline__ void hg_issue_chunk(
    const __nv_bfloat16* Ap, const __nv_bfloat16* Wp,
    int m0, int n0, int lda, int ldw, int k0,
    uint32_t sA, uint32_t sB, int tid)
{
#pragma unroll
    for (int i = 0; i < 4; ++i) {
        const int u = tid + i * 256;
        const int row = u >> 3, kg = u & 7;
        const uint32_t sw = row * 128 + (((uint32_t)(kg ^ (row & 7))) << 4);
        CP_ASYNC16(sA + sw, Ap + (size_t)(m0 + row) * lda + k0 + kg * 8);
    }
#pragma unroll
    for (int i = 0; i < 4; ++i) {
        const int u = tid + i * 256;
        const int row = u >> 3, kg = u & 7;
        const uint32_t sw = row * 128 + (((uint32_t)(kg ^ (row & 7))) << 4);
        CP_ASYNC16(sB + sw, Wp + (size_t)(n0 + row) * ldw + k0 + kg * 8);
    }
    CP_COMMIT();
}

__global__ void __launch_bounds__(256, 2) hgemm(
    const __nv_bfloat16* __restrict__ Ah, const __nv_bfloat16* __restrict__ Al,
    const __nv_bfloat16* __restrict__ Wh, const __nv_bfloat16* __restrict__ Wl,
    float* __restrict__ C,
    __nv_bfloat16* __restrict__ Chi, __nv_bfloat16* __restrict__ Clo,
    int lda, int ldw, int ldc, int Kd,
    long aO, long aI, long wO, long wI, long cO, long cI, int zInner,
    const float* __restrict__ bias,
    const float* __restrict__ mask, long maskStride, int mode)
{
    extern __shared__ char smraw[];
    const uint32_t sbase = (smem_u32(smraw) + 1023u) & ~1023u;

    const int tid = threadIdx.x;
    const int w = tid >> 5, lane = tid & 31;
    const long z = blockIdx.z;
    const long zo = z / zInner, zi = z % zInner;
    const long aoff = zo * aO + zi * aI;
    const long woff = zo * wO + zi * wI;
    const long coff = zo * cO + zi * cI;
    Ah += aoff; Al += aoff;
    Wh += woff; Wl += woff;
    if (C)   C   += coff;
    if (Chi) { Chi += coff; Clo += coff; }
    const float* mk = mask ? (mask + zo * maskStride) : nullptr;
    const int m0 = blockIdx.y * 128, n0 = blockIdx.x * 128;

    const int wm = (w >> 2) * 64;     // warp row base within tile (0 or 64)
    const int wn = (w & 3) * 32;      // warp col base within tile

    float acc[4][4][4];
#pragma unroll
    for (int a = 0; a < 4; ++a)
#pragma unroll
        for (int b = 0; b < 4; ++b)
#pragma unroll
            for (int c = 0; c < 4; ++c) acc[a][b][c] = 0.f;

    const int kc = Kd >> 6;           // K-chunks per phase
    const int nchunks = 3 * kc;

    // source pointers per phase: 0: Ah*Wh, 1: Ah*Wl, 2: Al*Wh
    auto srcA = [&](int phase) { return phase == 2 ? Al : Ah; };
    auto srcW = [&](int phase) { return phase == 1 ? Wl : Wh; };

    // prologue: issue chunks 0 and 1 into slots 0, 1 (slot 2 stays free)
    {
        hg_issue_chunk(srcA(0), srcW(0), m0, n0, lda, ldw, 0,
                       sbase, sbase + 16384, tid);
        const int p1 = 1 / kc;
        const int k1 = (1 - p1 * kc) << 6;
        hg_issue_chunk(srcA(p1), srcW(p1), m0, n0, lda, ldw, k1,
                       sbase + HG_STAGE_BYTES, sbase + HG_STAGE_BYTES + 16384, tid);
    }

    // per-lane ldmatrix row fragments
    const int rl = lane & 15;         // row within 16-row group
    const int kh = lane >> 4;         // 0/1 -> k-subgroup select

    for (int c = 0; c < nchunks; ++c) {
        CP_WAIT(1);                   // chunk c's group retired (exactly 1 commit/iter)
        __syncthreads();              // orders last iter's reads of slot (c+2)%3

        if (c + 2 < nchunks) {
            const int cn = c + 2;
            const int ph = cn / kc;
            const int k0 = (cn - ph * kc) << 6;
            const uint32_t slot = sbase + (uint32_t)(cn % HG_STAGES) * HG_STAGE_BYTES;
            hg_issue_chunk(srcA(ph), srcW(ph), m0, n0, lda, ldw, k0,
                           slot, slot + 16384, tid);
        } else {
            CP_COMMIT();              // empty group keeps wait_group accounting exact
        }

        const uint32_t sA = sbase + (uint32_t)(c % HG_STAGES) * HG_STAGE_BYTES;
        const uint32_t sB = sA + 16384;

#pragma unroll
        for (int ks = 0; ks < 4; ++ks) {
            const int kg = 2 * ks + kh;
            uint32_t ar[4][4];
#pragma unroll
            for (int tm = 0; tm < 4; ++tm) {
                const int row = wm + tm * 16 + rl;
                ldmatrix4(ar[tm], sA + row * 128 + (((uint32_t)(kg ^ (row & 7))) << 4));
            }
            uint32_t br[2][4];
#pragma unroll
            for (int tp = 0; tp < 2; ++tp) {
                const int row = wn + tp * 16 + rl;
                ldmatrix4(br[tp], sB + row * 128 + (((uint32_t)(kg ^ (row & 7))) << 4));
            }
#pragma unroll
            for (int tm = 0; tm < 4; ++tm)
#pragma unroll
                for (int tn = 0; tn < 4; ++tn) {
                    const uint32_t* bb = br[tn >> 1];
                    const int u = tn & 1;
                    mma16816(acc[tm][tn], ar[tm], bb[u], bb[u + 2]);
                }
        }
    }

    // ---------------- epilogue ----------------
    const int r0l = lane >> 2;        // 0..7
    const int c0l = (lane & 3) * 2;
    if (mode == 3) {
        // write bf16 hi/lo pair
#pragma unroll
        for (int tm = 0; tm < 4; ++tm) {
            const int row0 = m0 + wm + tm * 16 + r0l;
            const int row1 = row0 + 8;
            __nv_bfloat16* h0 = Chi + (size_t)row0 * ldc;
            __nv_bfloat16* h1 = Chi + (size_t)row1 * ldc;
            __nv_bfloat16* l0 = Clo + (size_t)row0 * ldc;
            __nv_bfloat16* l1 = Clo + (size_t)row1 * ldc;
#pragma unroll
            for (int tn = 0; tn < 4; ++tn) {
                const int col = n0 + wn + tn * 8 + c0l;
                const float d0 = acc[tm][tn][0], d1 = acc[tm][tn][1];
                const float d2 = acc[tm][tn][2], d3 = acc[tm][tn][3];
                __nv_bfloat16 a0 = __float2bfloat16(d0), a1 = __float2bfloat16(d1);
                __nv_bfloat16 a2 = __float2bfloat16(d2), a3 = __float2bfloat16(d3);
                *(__nv_bfloat162*)(h0 + col) = __halves2bfloat162(a0, a1);
                *(__nv_bfloat162*)(h1 + col) = __halves2bfloat162(a2, a3);
                *(__nv_bfloat162*)(l0 + col) = __halves2bfloat162(
                    __float2bfloat16(d0 - __bfloat162float(a0)),
                    __float2bfloat16(d1 - __bfloat162float(a1)));
                *(__nv_bfloat162*)(l1 + col) = __halves2bfloat162(
                    __float2bfloat16(d2 - __bfloat162float(a2)),
                    __float2bfloat16(d3 - __bfloat162float(a3)));
            }
        }
        return;
    }
#pragma unroll
    for (int tm = 0; tm < 4; ++tm) {
        const int row0 = m0 + wm + tm * 16 + r0l;
        const int row1 = row0 + 8;
        float mk0 = 0.f, mk1 = 0.f;
        if (mk) { mk0 = mk[row0]; mk1 = mk[row1]; }
        float* cr0 = C + (size_t)row0 * ldc;
        float* cr1 = C + (size_t)row1 * ldc;
#pragma unroll
        for (int tn = 0; tn < 4; ++tn) {
            const int col = n0 + wn + tn * 8 + c0l;
            float d0 = acc[tm][tn][0], d1 = acc[tm][tn][1];
            float d2 = acc[tm][tn][2], d3 = acc[tm][tn][3];
            if (bias) {
                const float b0 = bias[col], b1 = bias[col + 1];
                d0 += b0; d1 += b1; d2 += b0; d3 += b1;
            }
            if (mode == 1) {
                const float p0 = (1.f - mk0) * NEGV, p1 = (1.f - mk1) * NEGV;
                d0 += p0; d1 += p0; d2 += p1; d3 += p1;
            } else if (mode == 2) {
                d0 *= mk0; d1 *= mk0; d2 *= mk1; d3 *= mk1;
            }
            float2 s0; s0.x = d0; s0.y = d1;
            float2 s1; s1.x = d2; s1.y = d3;
            *(float2*)(cr0 + col) = s0;
            *(float2*)(cr1 + col) = s1;
        }
    }
}

// ---------------- layernorm -> bf16 hi/lo ----------------
template <int DLEN>
__global__ void __launch_bounds__(256) ln_hilo(const float* __restrict__ x,
                                               const float* __restrict__ gam,
                                               const float* __restrict__ bet,
                                               __nv_bfloat16* __restrict__ hi,
                                               __nv_bfloat16* __restrict__ lo)
{
    constexpr int PER = DLEN / 256;
    const size_t row = blockIdx.x;
    const float* xr = x + row * DLEN;
    float v[PER];
    float s = 0.f, sq = 0.f;
#pragma unroll
    for (int i = 0; i < PER; i++) {
        v[i] = xr[threadIdx.x + i * 256];
        s += v[i]; sq += v[i] * v[i];
    }
#pragma unroll
    for (int o = 16; o > 0; o >>= 1) {
        s  += __shfl_xor_sync(0xffffffffu, s, o);
        sq += __shfl_xor_sync(0xffffffffu, sq, o);
    }
    __shared__ float rs[8], rq[8];
    int w = threadIdx.x >> 5, l = threadIdx.x & 31;
    if (l == 0) { rs[w] = s; rq[w] = sq; }
    __syncthreads();
    float ts = 0.f, tq = 0.f;
#pragma unroll
    for (int i = 0; i < 8; i++) { ts += rs[i]; tq += rq[i]; }
    const float mean = ts / (float)DLEN;
    const float var = tq / (float)DLEN - mean * mean;
    const float rstd = rsqrtf(var + 1e-5f);
#pragma unroll
    for (int i = 0; i < PER; i++) {
        int c = threadIdx.x + i * 256;
        float o = (v[i] - mean) * rstd * gam[c] + bet[c];
        __nv_bfloat16 h = __float2bfloat16(o);
        hi[row * DLEN + c] = h;
        lo[row * DLEN + c] = __float2bfloat16(o - __bfloat162float(h));
    }
}

// ---------------- fp32 -> bf16 hi/lo convert ----------------
__global__ void __launch_bounds__(256) cvt_hilo(const float4* __restrict__ s,
                                                __nv_bfloat162* __restrict__ hi,
                                                __nv_bfloat162* __restrict__ lo, int n4)
{
    int i = blockIdx.x * blockDim.x + threadIdx.x;
    if (i < n4) {
        float4 v = s[i];
        __nv_bfloat16 h0 = __float2bfloat16(v.x), h1 = __float2bfloat16(v.y);
        __nv_bfloat16 h2 = __float2bfloat16(v.z), h3 = __float2bfloat16(v.w);
        hi[2 * i]     = __halves2bfloat162(h0, h1);
        hi[2 * i + 1] = __halves2bfloat162(h2, h3);
        lo[2 * i]     = __halves2bfloat162(__float2bfloat16(v.x - __bfloat162float(h0)),
                                           __float2bfloat16(v.y - __bfloat162float(h1)));
        lo[2 * i + 1] = __halves2bfloat162(__float2bfloat16(v.z - __bfloat162float(h2)),
                                           __float2bfloat16(v.w - __bfloat162float(h3)));
    }
}

// ---------------- q softmax over last dim (128) -> bf16 hi/lo ----------------
__global__ void __launch_bounds__(256) qsoftmax_kernel(const float* __restrict__ query,
                                                       __nv_bfloat16* __restrict__ qh,
                                                       __nv_bfloat16* __restrict__ ql)
{
    const size_t row = blockIdx.x;
    int w = threadIdx.x >> 5, l = threadIdx.x & 31;
    const float* src = query + row * D_ + (size_t)w * HD_;
    float4 v = *(const float4*)&src[l * 4];
    float m = fmaxf(fmaxf(v.x, v.y), fmaxf(v.z, v.w));
#pragma unroll
    for (int o = 16; o > 0; o >>= 1) m = fmaxf(m, __shfl_xor_sync(0xffffffffu, m, o));
    float e0 = expf(v.x - m), e1 = expf(v.y - m), e2 = expf(v.z - m), e3 = expf(v.w - m);
    float s = e0 + e1 + e2 + e3;
#pragma unroll
    for (int o = 16; o > 0; o >>= 1) s += __shfl_xor_sync(0xffffffffu, s, o);
    float inv = 1.0f / s;
    float q0 = e0 * inv, q1 = e1 * inv, q2 = e2 * inv, q3 = e3 * inv;
    __nv_bfloat16 h0 = __float2bfloat16(q0), h1 = __float2bfloat16(q1);
    __nv_bfloat16 h2 = __float2bfloat16(q2), h3 = __float2bfloat16(q3);
    const size_t off = row * D_ + (size_t)w * HD_ + l * 4;
    *(__nv_bfloat162*)(qh + off)     = __halves2bfloat162(h0, h1);
    *(__nv_bfloat162*)(qh + off + 2) = __halves2bfloat162(h2, h3);
    *(__nv_bfloat162*)(ql + off)     = __halves2bfloat162(
        __float2bfloat16(q0 - __bfloat162float(h0)),
        __float2bfloat16(q1 - __bfloat162float(h1)));
    *(__nv_bfloat162*)(ql + off + 2) = __halves2bfloat162(
        __float2bfloat16(q2 - __bfloat162float(h2)),
        __float2bfloat16(q3 - __bfloat162float(h3)));
}

// ---------------- key softmax over n ----------------
__global__ void __launch_bounds__(256) ksoftmax_kernel(float* __restrict__ key,
                                                       float* __restrict__ colsum)
{
    const int b = blockIdx.y;
    const int c0 = blockIdx.x * 64;
    const int idx = threadIdx.x & 63;
    const int r = threadIdx.x >> 6;
    float* base = key + (size_t)b * N_ * D_ + c0 + idx;
    float m = -3.0e38f;
    for (int n = r; n < N_; n += 4) m = fmaxf(m, base[(size_t)n * D_]);
    __shared__ float red[4][64];
    red[r][idx] = m;
    __syncthreads();
    m = fmaxf(fmaxf(red[0][idx], red[1][idx]), fmaxf(red[2][idx], red[3][idx]));
    __syncthreads();
    float s = 0.f;
    for (int n = r; n < N_; n += 4) {
        float e = expf(base[(size_t)n * D_] - m);
        base[(size_t)n * D_] = e;
        s += e;
    }
    red[r][idx] = s;
    __syncthreads();
    if (r == 0)
        colsum[b * D_ + c0 + idx] = red[0][idx] + red[1][idx] + red[2][idx] + red[3][idx];
}

__global__ void zero_kernel(float* __restrict__ p, int n)
{
    int i = blockIdx.x * blockDim.x + threadIdx.x;
    if (i < n) p[i] = 0.f;
}

// ---------------- fp32 FFMA2 micro-kernel (for attn) ----------------
__device__ __forceinline__ void micro8x8(const float (*As)[128], const float (*Bs)[128],
                                         int m_base, int n_base,
                                         unsigned long long acc[8][4])
{
#pragma unroll
    for (int kk = 0; kk < 8; kk++) {
        float4 a0 = *(const float4*)&As[kk][m_base];
        float4 a1 = *(const float4*)&As[kk][m_base + 4];
        float am[8] = {a0.x, a0.y, a0.z, a0.w, a1.x, a1.y, a1.z, a1.w};
        union { float4 f[2]; unsigned long long u[4]; } bb;
        bb.f[0] = *(const float4*)&Bs[kk][n_base];
        bb.f[1] = *(const float4*)&Bs[kk][n_base + 4];
#pragma unroll
        for (int i = 0; i < 8; i++) {
            unsigned long long aa;
            unsigned int ar = __float_as_uint(am[i]);
            asm("mov.b64 %0, {%1, %1};" : "=l"(aa) : "r"(ar));
#pragma unroll
            for (int j = 0; j < 4; j++)
                asm("fma.rn.f32x2 %0, %1, %2, %0;"
                    : "+l"(acc[i][j]) : "l"(aa), "l"(bb.u[j]));
        }
    }
}

// ---------------- attn: attnT[b,h,l,d] = (1/colsum) * sum_n k*v ----------------
// split-K over n (5 chunks of 512), atomicAdd accumulation
__global__ void __launch_bounds__(256) attn_kernel(const float* __restrict__ key,
                                                   const float* __restrict__ v,
                                                   const float* __restrict__ colsum,
                                                   float* __restrict__ attnT)
{
    __shared__ float As[8][128];
    __shared__ float Bs[8][128];
    const int tid = threadIdx.x;
    const int split = blockIdx.x, h = blockIdx.y, b = blockIdx.z;
    const int n0 = split * 512;
    const float* kg = key + (size_t)b * N_ * D_ + (size_t)h * HD_;
    const float* vg = v   + (size_t)b * N_ * D_ + (size_t)h * HD_;
    const int lrow = tid >> 5;
    const int lc = (tid & 31) * 4;

    unsigned long long acc[8][4];
#pragma unroll
    for (int i = 0; i < 8; i++)
#pragma unroll
        for (int j = 0; j < 4; j++) acc[i][j] = 0ull;

    const int m_base = (tid >> 4) * 8, n_base = (tid & 15) * 8;

    float4 av = *(const float4*)&kg[(size_t)(n0 + lrow) * D_ + lc];
    float4 wv = *(const float4*)&vg[(size_t)(n0 + lrow) * D_ + lc];
    for (int nn = 0; nn < 512; nn += 8) {
        *(float4*)&As[lrow][lc] = av;
        *(float4*)&Bs[lrow][lc] = wv;
        __syncthreads();
        if (nn + 8 < 512) {
            av = *(const float4*)&kg[(size_t)(n0 + nn + 8 + lrow) * D_ + lc];
            wv = *(const float4*)&vg[(size_t)(n0 + nn + 8 + lrow) * D_ + lc];
        }
        micro8x8(As, Bs, m_base, n_base, acc);
        __syncthreads();
    }

    float* outb = attnT + ((size_t)(b * H_ + h)) * HD_ * HD_;
#pragma unroll
    for (int i = 0; i < 8; i++) {
        const int dd = m_base + i;
        const float inv = 1.0f / colsum[b * D_ + h * HD_ + dd];
#pragma unroll
        for (int j = 0; j < 4; j++) {
            unsigned int u0, u1;
            asm("mov.b64 {%0, %1}, %2;" : "=r"(u0), "=r"(u1) : "l"(acc[i][j]));
            const int ll = n_base + 2 * j;
            atomicAdd(&outb[(size_t)ll * HD_ + dd], __uint_as_float(u0) * inv);
            atomicAdd(&outb[(size_t)(ll + 1) * HD_ + dd], __uint_as_float(u1) * inv);
        }
    }
}

// ---------------- host launch ----------------
extern "C" void kernel_launch(void* const* d_in, const int* in_sizes, int n_in,
                              void* d_out, int out_size)
{
    const float* query     = (const float*)d_in[0];
    const float* x         = (const float*)d_in[1];
    const float* cond_emb  = (const float*)d_in[2];
    const float* src_mask  = (const float*)d_in[3];
    const float* cond_mask = (const float*)d_in[4];
    const float* nxg = (const float*)d_in[5];
    const float* nxb = (const float*)d_in[6];
    const float* ncg = (const float*)d_in[7];
    const float* ncb = (const float*)d_in[8];
    const float* W_kc = (const float*)d_in[9];
    const float* b_kc = (const float*)d_in[10];
    const float* W_vc = (const float*)d_in[11];
    const float* b_vc = (const float*)d_in[12];
    const float* W_kx = (const float*)d_in[13];
    const float* b_kx = (const float*)d_in[14];
    const float* W_vx = (const float*)d_in[15];
    const float* b_vx = (const float*)d_in[16];
    const float* W_y  = (const float*)d_in[17];
    const float* b_y  = (const float*)d_in[18];
    float* out = (float*)d_out;

    float *keyb, *vb, *cs, *attnT;
    __nv_bfloat16 *xnh, *xnl, *cnh, *cnl, *qh, *ql, *ath, *atl, *yh, *yl;
    __nv_bfloat16 *wkxh, *wkxl, *wvxh, *wvxl, *wyh, *wyl, *wkch, *wkcl, *wvch, *wvcl;
    cudaGetSymbolAddress((void**)&keyb, g_key);
    cudaGetSymbolAddress((void**)&vb, g_v);
    cudaGetSymbolAddress((void**)&cs, g_colsum);
    cudaGetSymbolAddress((void**)&attnT, g_attnT);
    cudaGetSymbolAddress((void**)&xnh, g_xn_h); cudaGetSymbolAddress((void**)&xnl, g_xn_l);
    cudaGetSymbolAddress((void**)&cnh, g_cn_h); cudaGetSymbolAddress((void**)&cnl, g_cn_l);
    cudaGetSymbolAddress((void**)&qh, g_q_h);   cudaGetSymbolAddress((void**)&ql, g_q_l);
    cudaGetSymbolAddress((void**)&ath, g_at_h); cudaGetSymbolAddress((void**)&atl, g_at_l);
    cudaGetSymbolAddress((void**)&yh, g_y_h);   cudaGetSymbolAddress((void**)&yl, g_y_l);
    cudaGetSymbolAddress((void**)&wkxh, g_wkx_h); cudaGetSymbolAddress((void**)&wkxl, g_wkx_l);
    cudaGetSymbolAddress((void**)&wvxh, g_wvx_h); cudaGetSymbolAddress((void**)&wvxl, g_wvx_l);
    cudaGetSymbolAddress((void**)&wyh, g_wy_h);   cudaGetSymbolAddress((void**)&wyl, g_wy_l);
    cudaGetSymbolAddress((void**)&wkch, g_wkc_h); cudaGetSymbolAddress((void**)&wkcl, g_wkc_l);
    cudaGetSymbolAddress((void**)&wvch, g_wvc_h); cudaGetSymbolAddress((void**)&wvcl, g_wvc_l);

    cudaFuncSetAttribute(hgemm, cudaFuncAttributeMaxDynamicSharedMemorySize, HG_SMEM_BYTES);

    // launches 0-4: ln, ln, qsoftmax, cvt W_kx, cvt W_vx
    // => launch idx 5 is the big hgemm (ncu -s 5 -c 1 captures idx 5, verified R12)
    ln_hilo<D_><<<B_ * T_, 256>>>(x, nxg, nxb, xnh, xnl);
    ln_hilo<DC_><<<B_ * TC_, 256>>>(cond_emb, ncg, ncb, cnh, cnl);
    qsoftmax_kernel<<<B_ * T_, 256>>>(query, qh, ql);
    {
        int n4 = (D_ * D_) / 4;
        cvt_hilo<<<(n4 + 255) / 256, 256>>>((const float4*)W_kx, (__nv_bfloat162*)wkxh, (__nv_bfloat162*)wkxl, n4);
        cvt_hilo<<<(n4 + 255) / 256, 256>>>((const float4*)W_vx, (__nv_bfloat162*)wvxh, (__nv_bfloat162*)wvxl, n4);
    }

    // launch 5: k_x projection (profiling target)
    hgemm<<<dim3(D_ / 128, T_ / 128, B_), 256, HG_SMEM_BYTES>>>(
        xnh, xnl, wkxh, wkxl, keyb + (size_t)TC_ * D_, nullptr, nullptr,
        D_, D_, D_, D_,
        (long)T_ * D_, 0, 0, 0, (long)N_ * D_, 0, 1,
        b_kx, src_mask, (long)T_, 1);

    {
        int n4 = (D_ * D_) / 4;
        cvt_hilo<<<(n4 + 255) / 256, 256>>>((const float4*)W_y, (__nv_bfloat162*)wyh, (__nv_bfloat162*)wyl, n4);
        int n4c = (D_ * DC_) / 4;
        cvt_hilo<<<(n4c + 255) / 256, 256>>>((const float4*)W_kc, (__nv_bfloat162*)wkch, (__nv_bfloat162*)wkcl, n4c);
        cvt_hilo<<<(n4c + 255) / 256, 256>>>((const float4*)W_vc, (__nv_bfloat162*)wvch, (__nv_bfloat162*)wvcl, n4c);
    }

    hgemm<<<dim3(D_ / 128, T_ / 128, B_), 256, HG_SMEM_BYTES>>>(
        xnh, xnl, wvxh, wvxl, vb + (size_t)TC_ * D_, nullptr, nullptr,
        D_, D_, D_, D_,
        (long)T_ * D_, 0, 0, 0, (long)N_ * D_, 0, 1,
        b_vx, src_mask, (long)T_, 2);
    hgemm<<<dim3(D_ / 128, TC_ / 128, B_), 256, HG_SMEM_BYTES>>>(
        cnh, cnl, wkch, wkcl, keyb, nullptr, nullptr,
        DC_, DC_, D_, DC_,
        (long)TC_ * DC_, 0, 0, 0, (long)N_ * D_, 0, 1,
        b_kc, cond_mask, (long)TC_, 1);
    hgemm<<<dim3(D_ / 128, TC_ / 128, B_), 256, HG_SMEM_BYTES>>>(
        cnh, cnl, wvch, wvcl, vb, nullptr, nullptr,
        DC_, DC_, D_, DC_,
        (long)TC_ * DC_, 0, 0, 0, (long)N_ * D_, 0, 1,
        b_vc, cond_mask, (long)TC_, 2);

    // softmax over sequence axis (exp in place + column sums)
    ksoftmax_kernel<<<dim3(D_ / 64, B_), 256>>>(keyb, cs);

    // attn = normalized k^T v (fp32, split-K(5) + atomics)
    zero_kernel<<<(B_ * H_ * HD_ * HD_ + 255) / 256, 256>>>(attnT, B_ * H_ * HD_ * HD_);
    attn_kernel<<<dim3(5, H_, B_), 256>>>(keyb, vb, cs, attnT);

    // attnT -> bf16 hi/lo (4 MB, tiny)
    {
        int n4 = (B_ * H_ * HD_ * HD_) / 4;
        cvt_hilo<<<(n4 + 255) / 256, 256>>>((const float4*)attnT, (__nv_bfloat162*)ath, (__nv_bfloat162*)atl, n4);
    }

    // y = q @ attn on tensor cores, batched over z = b*H + h; writes bf16 hi/lo directly
    hgemm<<<dim3(1, T_ / 128, B_ * H_), 256, HG_SMEM_BYTES>>>(
        qh, ql, ath, atl, nullptr, yh, yl,
        D_, HD_, D_, HD_,
        (long)T_ * D_, (long)HD_,                 // A: zo=b -> +T*D, zi=h -> +HD
        (long)H_ * HD_ * HD_, (long)HD_ * HD_,    // W: zo=b, zi=h
        (long)T_ * D_, (long)HD_,                 // C: zo=b, zi=h
        H_, nullptr, nullptr, 0, 3);

    // out = y @ W_y^T + b_y on tensor cores
    hgemm<<<dim3(D_ / 128, (B_ * T_) / 128, 1), 256, HG_SMEM_BYTES>>>(
        yh, yl, wyh, wyl, out, nullptr, nullptr,
        D_, D_, D_, D_,
        0, 0, 0, 0, 0, 0, 1,
        b_y, nullptr, 0, 0);
}

// round 15
// speedup vs baseline: 1.9811x; 1.3391x over previous
#include <cuda_runtime.h>
#include <cuda_fp16.h>
#include <cstdint>

// ---------------- problem constants ----------------
#define B_   8
#define T_   2048
#define TC_  512
#define D_   1024
#define DC_  512
#define N_   2560   // T_ + TC_
#define H_   8
#define HD_  128
#define NEGV (-1000000.0f)

// ---------------- scratch (device globals: allocation-free rule) ----------------
__device__ float g_key[(size_t)B_ * N_ * D_];
__device__ float g_v[(size_t)B_ * N_ * D_];
__device__ float g_colsum[B_ * D_];
__device__ float g_attnT[(size_t)B_ * H_ * HD_ * HD_];

__device__ __half g_xn_h[(size_t)B_ * T_ * D_];
__device__ __half g_xn_l[(size_t)B_ * T_ * D_];
__device__ __half g_cn_h[(size_t)B_ * TC_ * DC_];
__device__ __half g_cn_l[(size_t)B_ * TC_ * DC_];
__device__ __half g_q_h[(size_t)B_ * T_ * D_];
__device__ __half g_q_l[(size_t)B_ * T_ * D_];
__device__ __half g_at_h[(size_t)B_ * H_ * HD_ * HD_];
__device__ __half g_y_h[(size_t)B_ * T_ * D_];
__device__ __half g_y_l[(size_t)B_ * T_ * D_];
__device__ __half g_wkx_h[D_ * D_];
__device__ __half g_wvx_h[D_ * D_];
__device__ __half g_wy_h[D_ * D_];
__device__ __half g_wkc_h[D_ * DC_];
__device__ __half g_wvc_h[D_ * DC_];

// ---------------- small PTX helpers (plain sm_103-safe: sm_80-era ISA only) ----------------
__device__ __forceinline__ uint32_t smem_u32(const void* p) {
    uint32_t a;
    asm("{ .reg .u64 t; cvta.to.shared.u64 t, %1; cvt.u32.u64 %0, t; }" : "=r"(a) : "l"(p));
    return a;
}
#define CP_ASYNC16(sm, gp) \
    asm volatile("cp.async.cg.shared.global [%0], [%1], 16;" :: "r"(sm), "l"(gp) : "memory")
#define CP_COMMIT() asm volatile("cp.async.commit_group;" ::: "memory")
#define CP_WAIT(n)  asm volatile("cp.async.wait_group %0;" :: "n"(n) : "memory")

__device__ __forceinline__ void ldmatrix4(uint32_t* r, uint32_t addr) {
    asm volatile("ldmatrix.sync.aligned.m8n8.x4.shared.b16 {%0,%1,%2,%3}, [%4];"
                 : "=r"(r[0]), "=r"(r[1]), "=r"(r[2]), "=r"(r[3]) : "r"(addr));
}
__device__ __forceinline__ void mma16816(float* d, const uint32_t* a, uint32_t b0, uint32_t b1) {
    asm volatile("mma.sync.aligned.m16n8k16.row.col.f32.f16.f16.f32 "
                 "{%0,%1,%2,%3}, {%4,%5,%6,%7}, {%8,%9}, {%0,%1,%2,%3};"
                 : "+f"(d[0]), "+f"(d[1]), "+f"(d[2]), "+f"(d[3])
                 : "r"(a[0]), "r"(a[1]), "r"(a[2]), "r"(a[3]), "r"(b0), "r"(b1));
}

// ---------------- fp16 2-term split HMMA GEMM ----------------
//  C = (Ah + Al)(M,K) * Wh(N,K)^T   (fp32 accum) — A carried to ~22 mantissa bits,
//  W single-fp16 (error ~1.4e-4 RMS, dominated by W representation).
//  CTA tile 128x128, warp tile 64x32, K-chunk 64, 3-stage cp.async multistage
//  (structure identical to the validated R11 kernel; only the phase table changed).
//  Batch: z -> zo = z / zInner, zi = z % zInner; offsets aO*zo + aI*zi etc.
//  epilogue modes: 0: +bias ; 1: +bias + (1-mask[m])*NEG ; 2: (+bias)*mask[m] ;
//                  3: write fp16 hi/lo pair to Chi/Clo (no bias/mask)
#define HG_STAGES      3
#define HG_STAGE_BYTES 32768          // A 16KB + B 16KB
#define HG_SMEM_BYTES  (1024 + HG_STAGES * HG_STAGE_BYTES)

__device__ __forceinline__ void hg_issue_chunk(
    const __half* Ap, const __half* Wp,
    int m0, int n0, int lda, int ldw, int k0,
    uint32_t sA, uint32_t sB, int tid)
{
#pragma unroll
    for (int i = 0; i < 4; ++i) {
        const int u = tid + i * 256;
        const int row = u >> 3, kg = u & 7;
        const uint32_t sw = row * 128 + (((uint32_t)(kg ^ (row & 7))) << 4);
        CP_ASYNC16(sA + sw, Ap + (size_t)(m0 + row) * lda + k0 + kg * 8);
    }
#pragma unroll
    for (int i = 0; i < 4; ++i) {
        const int u = tid + i * 256;
        const int row = u >> 3, kg = u & 7;
        const uint32_t sw = row * 128 + (((uint32_t)(kg ^ (row & 7))) << 4);
        CP_ASYNC16(sB + sw, Wp + (size_t)(n0 + row) * ldw + k0 + kg * 8);
    }
    CP_COMMIT();
}

__global__ void __launch_bounds__(256, 2) hgemm(
    const __half* __restrict__ Ah, const __half* __restrict__ Al,
    const __half* __restrict__ Wh,
    float* __restrict__ C,
    __half* __restrict__ Chi, __half* __restrict__ Clo,
    int lda, int ldw, int ldc, int Kd,
    long aO, long aI, long wO, long wI, long cO, long cI, int zInner,
    const float* __restrict__ bias,
    const float* __restrict__ mask, long maskStride, int mode)
{
    extern __shared__ char smraw[];
    const uint32_t sbase = (smem_u32(smraw) + 1023u) & ~1023u;

    const int tid = threadIdx.x;
    const int w = tid >> 5, lane = tid & 31;
    const long z = blockIdx.z;
    const long zo = z / zInner, zi = z % zInner;
    const long aoff = zo * aO + zi * aI;
    const long woff = zo * wO + zi * wI;
    const long coff = zo * cO + zi * cI;
    Ah += aoff; Al += aoff;
    Wh += woff;
    if (C)   C   += coff;
    if (Chi) { Chi += coff; Clo += coff; }
    const float* mk = mask ? (mask + zo * maskStride) : nullptr;
    const int m0 = blockIdx.y * 128, n0 = blockIdx.x * 128;

    const int wm = (w >> 2) * 64;     // warp row base within tile (0 or 64)
    const int wn = (w & 3) * 32;      // warp col base within tile

    float acc[4][4][4];
#pragma unroll
    for (int a = 0; a < 4; ++a)
#pragma unroll
        for (int b = 0; b < 4; ++b)
#pragma unroll
            for (int c = 0; c < 4; ++c) acc[a][b][c] = 0.f;

    const int kc = Kd >> 6;           // K-chunks per phase
    const int nchunks = 2 * kc;       // phase 0: Ah*Wh, phase 1: Al*Wh

    auto srcA = [&](int phase) { return phase ? Al : Ah; };

    // prologue: issue chunks 0 and 1 into slots 0, 1 (slot 2 stays free)
    {
        hg_issue_chunk(srcA(0), Wh, m0, n0, lda, ldw, 0,
                       sbase, sbase + 16384, tid);
        const int p1 = 1 / kc;
        const int k1 = (1 - p1 * kc) << 6;
        hg_issue_chunk(srcA(p1), Wh, m0, n0, lda, ldw, k1,
                       sbase + HG_STAGE_BYTES, sbase + HG_STAGE_BYTES + 16384, tid);
    }

    // per-lane ldmatrix row fragments
    const int rl = lane & 15;         // row within 16-row group
    const int kh = lane >> 4;         // 0/1 -> k-subgroup select

    for (int c = 0; c < nchunks; ++c) {
        CP_WAIT(1);                   // chunk c's group retired (exactly 1 commit/iter)
        __syncthreads();              // orders last iter's reads of slot (c+2)%3

        if (c + 2 < nchunks) {
            const int cn = c + 2;
            const int ph = cn / kc;
            const int k0 = (cn - ph * kc) << 6;
            const uint32_t slot = sbase + (uint32_t)(cn % HG_STAGES) * HG_STAGE_BYTES;
            hg_issue_chunk(srcA(ph), Wh, m0, n0, lda, ldw, k0,
                           slot, slot + 16384, tid);
        } else {
            CP_COMMIT();              // empty group keeps wait_group accounting exact
        }

        const uint32_t sA = sbase + (uint32_t)(c % HG_STAGES) * HG_STAGE_BYTES;
        const uint32_t sB = sA + 16384;

#pragma unroll
        for (int ks = 0; ks < 4; ++ks) {
            const int kg = 2 * ks + kh;
            uint32_t ar[4][4];
#pragma unroll
            for (int tm = 0; tm < 4; ++tm) {
                const int row = wm + tm * 16 + rl;
                ldmatrix4(ar[tm], sA + row * 128 + (((uint32_t)(kg ^ (row & 7))) << 4));
            }
            uint32_t br[2][4];
#pragma unroll
            for (int tp = 0; tp < 2; ++tp) {
                const int row = wn + tp * 16 + rl;
                ldmatrix4(br[tp], sB + row * 128 + (((uint32_t)(kg ^ (row & 7))) << 4));
            }
#pragma unroll
            for (int tm = 0; tm < 4; ++tm)
#pragma unroll
                for (int tn = 0; tn < 4; ++tn) {
                    const uint32_t* bb = br[tn >> 1];
                    const int u = tn & 1;
                    mma16816(acc[tm][tn], ar[tm], bb[u], bb[u + 2]);
                }
        }
    }

    // ---------------- epilogue ----------------
    const int r0l = lane >> 2;        // 0..7
    const int c0l = (lane & 3) * 2;
    if (mode == 3) {
        // write fp16 hi/lo pair
#pragma unroll
        for (int tm = 0; tm < 4; ++tm) {
            const int row0 = m0 + wm + tm * 16 + r0l;
            const int row1 = row0 + 8;
            __half* h0 = Chi + (size_t)row0 * ldc;
            __half* h1 = Chi + (size_t)row1 * ldc;
            __half* l0 = Clo + (size_t)row0 * ldc;
            __half* l1 = Clo + (size_t)row1 * ldc;
#pragma unroll
            for (int tn = 0; tn < 4; ++tn) {
                const int col = n0 + wn + tn * 8 + c0l;
                const float d0 = acc[tm][tn][0], d1 = acc[tm][tn][1];
                const float d2 = acc[tm][tn][2], d3 = acc[tm][tn][3];
                __half a0 = __float2half(d0), a1 = __float2half(d1);
                __half a2 = __float2half(d2), a3 = __float2half(d3);
                *(__half2*)(h0 + col) = __halves2half2(a0, a1);
                *(__half2*)(h1 + col) = __halves2half2(a2, a3);
                *(__half2*)(l0 + col) = __halves2half2(
                    __float2half(d0 - __half2float(a0)),
                    __float2half(d1 - __half2float(a1)));
                *(__half2*)(l1 + col) = __halves2half2(
                    __float2half(d2 - __half2float(a2)),
                    __float2half(d3 - __half2float(a3)));
            }
        }
        return;
    }
#pragma unroll
    for (int tm = 0; tm < 4; ++tm) {
        const int row0 = m0 + wm + tm * 16 + r0l;
        const int row1 = row0 + 8;
        float mk0 = 0.f, mk1 = 0.f;
        if (mk) { mk0 = mk[row0]; mk1 = mk[row1]; }
        float* cr0 = C + (size_t)row0 * ldc;
        float* cr1 = C + (size_t)row1 * ldc;
#pragma unroll
        for (int tn = 0; tn < 4; ++tn) {
            const int col = n0 + wn + tn * 8 + c0l;
            float d0 = acc[tm][tn][0], d1 = acc[tm][tn][1];
            float d2 = acc[tm][tn][2], d3 = acc[tm][tn][3];
            if (bias) {
                const float b0 = bias[col], b1 = bias[col + 1];
                d0 += b0; d1 += b1; d2 += b0; d3 += b1;
            }
            if (mode == 1) {
                const float p0 = (1.f - mk0) * NEGV, p1 = (1.f - mk1) * NEGV;
                d0 += p0; d1 += p0; d2 += p1; d3 += p1;
            } else if (mode == 2) {
                d0 *= mk0; d1 *= mk0; d2 *= mk1; d3 *= mk1;
            }
            float2 s0; s0.x = d0; s0.y = d1;
            float2 s1; s1.x = d2; s1.y = d3;
            *(float2*)(cr0 + col) = s0;
            *(float2*)(cr1 + col) = s1;
        }
    }
}

// ---------------- layernorm -> fp16 hi/lo ----------------
template <int DLEN>
__global__ void __launch_bounds__(256) ln_hilo(const float* __restrict__ x,
                                               const float* __restrict__ gam,
                                               const float* __restrict__ bet,
                                               __half* __restrict__ hi,
                                               __half* __restrict__ lo)
{
    constexpr int PER = DLEN / 256;
    const size_t row = blockIdx.x;
    const float* xr = x + row * DLEN;
    float v[PER];
    float s = 0.f, sq = 0.f;
#pragma unroll
    for (int i = 0; i < PER; i++) {
        v[i] = xr[threadIdx.x + i * 256];
        s += v[i]; sq += v[i] * v[i];
    }
#pragma unroll
    for (int o = 16; o > 0; o >>= 1) {
        s  += __shfl_xor_sync(0xffffffffu, s, o);
        sq += __shfl_xor_sync(0xffffffffu, sq, o);
    }
    __shared__ float rs[8], rq[8];
    int w = threadIdx.x >> 5, l = threadIdx.x & 31;
    if (l == 0) { rs[w] = s; rq[w] = sq; }
    __syncthreads();
    float ts = 0.f, tq = 0.f;
#pragma unroll
    for (int i = 0; i < 8; i++) { ts += rs[i]; tq += rq[i]; }
    const float mean = ts / (float)DLEN;
    const float var = tq / (float)DLEN - mean * mean;
    const float rstd = rsqrtf(var + 1e-5f);
#pragma unroll
    for (int i = 0; i < PER; i++) {
        int c = threadIdx.x + i * 256;
        float o = (v[i] - mean) * rstd * gam[c] + bet[c];
        __half h = __float2half(o);
        hi[row * DLEN + c] = h;
        lo[row * DLEN + c] = __float2half(o - __half2float(h));
    }
}

// ---------------- fp32 -> fp16 convert (hi only, for weights / attnT) ----------------
__global__ void __launch_bounds__(256) cvt_h(const float4* __restrict__ s,
                                             __half2* __restrict__ hi, int n4)
{
    int i = blockIdx.x * blockDim.x + threadIdx.x;
    if (i < n4) {
        float4 v = s[i];
        hi[2 * i]     = __halves2half2(__float2half(v.x), __float2half(v.y));
        hi[2 * i + 1] = __halves2half2(__float2half(v.z), __float2half(v.w));
    }
}

// ---------------- q softmax over last dim (128) -> fp16 hi/lo ----------------
__global__ void __launch_bounds__(256) qsoftmax_kernel(const float* __restrict__ query,
                                                       __half* __restrict__ qh,
                                                       __half* __restrict__ ql)
{
    const size_t row = blockIdx.x;
    int w = threadIdx.x >> 5, l = threadIdx.x & 31;
    const float* src = query + row * D_ + (size_t)w * HD_;
    float4 v = *(const float4*)&src[l * 4];
    float m = fmaxf(fmaxf(v.x, v.y), fmaxf(v.z, v.w));
#pragma unroll
    for (int o = 16; o > 0; o >>= 1) m = fmaxf(m, __shfl_xor_sync(0xffffffffu, m, o));
    float e0 = expf(v.x - m), e1 = expf(v.y - m), e2 = expf(v.z - m), e3 = expf(v.w - m);
    float s = e0 + e1 + e2 + e3;
#pragma unroll
    for (int o = 16; o > 0; o >>= 1) s += __shfl_xor_sync(0xffffffffu, s, o);
    float inv = 1.0f / s;
    float q0 = e0 * inv, q1 = e1 * inv, q2 = e2 * inv, q3 = e3 * inv;
    __half h0 = __float2half(q0), h1 = __float2half(q1);
    __half h2 = __float2half(q2), h3 = __float2half(q3);
    const size_t off = row * D_ + (size_t)w * HD_ + l * 4;
    *(__half2*)(qh + off)     = __halves2half2(h0, h1);
    *(__half2*)(qh + off + 2) = __halves2half2(h2, h3);
    *(__half2*)(ql + off)     = __halves2half2(
        __float2half(q0 - __half2float(h0)),
        __float2half(q1 - __half2float(h1)));
    *(__half2*)(ql + off + 2) = __halves2half2(
        __float2half(q2 - __half2float(h2)),
        __float2half(q3 - __half2float(h3)));
}

// ---------------- key softmax over n ----------------
__global__ void __launch_bounds__(256) ksoftmax_kernel(float* __restrict__ key,
                                                       float* __restrict__ colsum)
{
    const int b = blockIdx.y;
    const int c0 = blockIdx.x * 64;
    const int idx = threadIdx.x & 63;
    const int r = threadIdx.x >> 6;
    float* base = key + (size_t)b * N_ * D_ + c0 + idx;
    float m = -3.0e38f;
    for (int n = r; n < N_; n += 4) m = fmaxf(m, base[(size_t)n * D_]);
    __shared__ float red[4][64];
    red[r][idx] = m;
    __syncthreads();
    m = fmaxf(fmaxf(red[0][idx], red[1][idx]), fmaxf(red[2][idx], red[3][idx]));
    __syncthreads();
    float s = 0.f;
    for (int n = r; n < N_; n += 4) {
        float e = expf(base[(size_t)n * D_] - m);
        base[(size_t)n * D_] = e;
        s += e;
    }
    red[r][idx] = s;
    __syncthreads();
    if (r == 0)
        colsum[b * D_ + c0 + idx] = red[0][idx] + red[1][idx] + red[2][idx] + red[3][idx];
}

__global__ void zero_kernel(float* __restrict__ p, int n)
{
    int i = blockIdx.x * blockDim.x + threadIdx.x;
    if (i < n) p[i] = 0.f;
}

// ---------------- fp32 FFMA2 micro-kernel (for attn) ----------------
__device__ __forceinline__ void micro8x8(const float (*As)[128], const float (*Bs)[128],
                                         int m_base, int n_base,
                                         unsigned long long acc[8][4])
{
#pragma unroll
    for (int kk = 0; kk < 8; kk++) {
        float4 a0 = *(const float4*)&As[kk][m_base];
        float4 a1 = *(const float4*)&As[kk][m_base + 4];
        float am[8] = {a0.x, a0.y, a0.z, a0.w, a1.x, a1.y, a1.z, a1.w};
        union { float4 f[2]; unsigned long long u[4]; } bb;
        bb.f[0] = *(const float4*)&Bs[kk][n_base];
        bb.f[1] = *(const float4*)&Bs[kk][n_base + 4];
#pragma unroll
        for (int i = 0; i < 8; i++) {
            unsigned long long aa;
            unsigned int ar = __float_as_uint(am[i]);
            asm("mov.b64 %0, {%1, %1};" : "=l"(aa) : "r"(ar));
#pragma unroll
            for (int j = 0; j < 4; j++)
                asm("fma.rn.f32x2 %0, %1, %2, %0;"
                    : "+l"(acc[i][j]) : "l"(aa), "l"(bb.u[j]));
        }
    }
}

// ---------------- attn: attnT[b,h,l,d] = (1/colsum) * sum_n k*v ----------------
// split-K over n (10 chunks of 256), atomicAdd accumulation
__global__ void __launch_bounds__(256) attn_kernel(const float* __restrict__ key,
                                                   const float* __restrict__ v,
                                                   const float* __restrict__ colsum,
                                                   float* __restrict__ attnT)
{
    __shared__ float As[8][128];
    __shared__ float Bs[8][128];
    const int tid = threadIdx.x;
    const int split = blockIdx.x, h = blockIdx.y, b = blockIdx.z;
    const int n0 = split * 256;
    const float* kg = key + (size_t)b * N_ * D_ + (size_t)h * HD_;
    const float* vg = v   + (size_t)b * N_ * D_ + (size_t)h * HD_;
    const int lrow = tid >> 5;
    const int lc = (tid & 31) * 4;

    unsigned long long acc[8][4];
#pragma unroll
    for (int i = 0; i < 8; i++)
#pragma unroll
        for (int j = 0; j < 4; j++) acc[i][j] = 0ull;

    const int m_base = (tid >> 4) * 8, n_base = (tid & 15) * 8;

    float4 av = *(const float4*)&kg[(size_t)(n0 + lrow) * D_ + lc];
    float4 wv = *(const float4*)&vg[(size_t)(n0 + lrow) * D_ + lc];
    for (int nn = 0; nn < 256; nn += 8) {
        *(float4*)&As[lrow][lc] = av;
        *(float4*)&Bs[lrow][lc] = wv;
        __syncthreads();
        if (nn + 8 < 256) {
            av = *(const float4*)&kg[(size_t)(n0 + nn + 8 + lrow) * D_ + lc];
            wv = *(const float4*)&vg[(size_t)(n0 + nn + 8 + lrow) * D_ + lc];
        }
        micro8x8(As, Bs, m_base, n_base, acc);
        __syncthreads();
    }

    float* outb = attnT + ((size_t)(b * H_ + h)) * HD_ * HD_;
#pragma unroll
    for (int i = 0; i < 8; i++) {
        const int dd = m_base + i;
        const float inv = 1.0f / colsum[b * D_ + h * HD_ + dd];
#pragma unroll
        for (int j = 0; j < 4; j++) {
            unsigned int u0, u1;
            asm("mov.b64 {%0, %1}, %2;" : "=r"(u0), "=r"(u1) : "l"(acc[i][j]));
            const int ll = n_base + 2 * j;
            atomicAdd(&outb[(size_t)ll * HD_ + dd], __uint_as_float(u0) * inv);
            atomicAdd(&outb[(size_t)(ll + 1) * HD_ + dd], __uint_as_float(u1) * inv);
        }
    }
}

// ---------------- host launch ----------------
extern "C" void kernel_launch(void* const* d_in, const int* in_sizes, int n_in,
                              void* d_out, int out_size)
{
    const float* query     = (const float*)d_in[0];
    const float* x         = (const float*)d_in[1];
    const float* cond_emb  = (const float*)d_in[2];
    const float* src_mask  = (const float*)d_in[3];
    const float* cond_mask = (const float*)d_in[4];
    const float* nxg = (const float*)d_in[5];
    const float* nxb = (const float*)d_in[6];
    const float* ncg = (const float*)d_in[7];
    const float* ncb = (const float*)d_in[8];
    const float* W_kc = (const float*)d_in[9];
    const float* b_kc = (const float*)d_in[10];
    const float* W_vc = (const float*)d_in[11];
    const float* b_vc = (const float*)d_in[12];
    const float* W_kx = (const float*)d_in[13];
    const float* b_kx = (const float*)d_in[14];
    const float* W_vx = (const float*)d_in[15];
    const float* b_vx = (const float*)d_in[16];
    const float* W_y  = (const float*)d_in[17];
    const float* b_y  = (const float*)d_in[18];
    float* out = (float*)d_out;

    float *keyb, *vb, *cs, *attnT;
    __half *xnh, *xnl, *cnh, *cnl, *qh, *ql, *ath, *yh, *yl;
    __half *wkxh, *wvxh, *wyh, *wkch, *wvch;
    cudaGetSymbolAddress((void**)&keyb, g_key);
    cudaGetSymbolAddress((void**)&vb, g_v);
    cudaGetSymbolAddress((void**)&cs, g_colsum);
    cudaGetSymbolAddress((void**)&attnT, g_attnT);
    cudaGetSymbolAddress((void**)&xnh, g_xn_h); cudaGetSymbolAddress((void**)&xnl, g_xn_l);
    cudaGetSymbolAddress((void**)&cnh, g_cn_h); cudaGetSymbolAddress((void**)&cnl, g_cn_l);
    cudaGetSymbolAddress((void**)&qh, g_q_h);   cudaGetSymbolAddress((void**)&ql, g_q_l);
    cudaGetSymbolAddress((void**)&ath, g_at_h);
    cudaGetSymbolAddress((void**)&yh, g_y_h);   cudaGetSymbolAddress((void**)&yl, g_y_l);
    cudaGetSymbolAddress((void**)&wkxh, g_wkx_h);
    cudaGetSymbolAddress((void**)&wvxh, g_wvx_h);
    cudaGetSymbolAddress((void**)&wyh, g_wy_h);
    cudaGetSymbolAddress((void**)&wkch, g_wkc_h);
    cudaGetSymbolAddress((void**)&wvch, g_wvc_h);

    cudaFuncSetAttribute(hgemm, cudaFuncAttributeMaxDynamicSharedMemorySize, HG_SMEM_BYTES);

    // elementwise prep
    ln_hilo<D_><<<B_ * T_, 256>>>(x, nxg, nxb, xnh, xnl);
    ln_hilo<DC_><<<B_ * TC_, 256>>>(cond_emb, ncg, ncb, cnh, cnl);
    qsoftmax_kernel<<<B_ * T_, 256>>>(query, qh, ql);
    {
        int n4 = (D_ * D_) / 4;
        cvt_h<<<(n4 + 255) / 256, 256>>>((const float4*)W_kx, (__half2*)wkxh, n4);
        cvt_h<<<(n4 + 255) / 256, 256>>>((const float4*)W_vx, (__half2*)wvxh, n4);
        cvt_h<<<(n4 + 255) / 256, 256>>>((const float4*)W_y,  (__half2*)wyh,  n4);
        int n4c = (D_ * DC_) / 4;
        cvt_h<<<(n4c + 255) / 256, 256>>>((const float4*)W_kc, (__half2*)wkch, n4c);
        cvt_h<<<(n4c + 255) / 256, 256>>>((const float4*)W_vc, (__half2*)wvch, n4c);
    }

    // fp16 2-term split GEMMs for k/v projections
    hgemm<<<dim3(D_ / 128, T_ / 128, B_), 256, HG_SMEM_BYTES>>>(
        xnh, xnl, wkxh, keyb + (size_t)TC_ * D_, nullptr, nullptr,
        D_, D_, D_, D_,
        (long)T_ * D_, 0, 0, 0, (long)N_ * D_, 0, 1,
        b_kx, src_mask, (long)T_, 1);
    hgemm<<<dim3(D_ / 128, T_ / 128, B_), 256, HG_SMEM_BYTES>>>(
        xnh, xnl, wvxh, vb + (size_t)TC_ * D_, nullptr, nullptr,
        D_, D_, D_, D_,
        (long)T_ * D_, 0, 0, 0, (long)N_ * D_, 0, 1,
        b_vx, src_mask, (long)T_, 2);
    hgemm<<<dim3(D_ / 128, TC_ / 128, B_), 256, HG_SMEM_BYTES>>>(
        cnh, cnl, wkch, keyb, nullptr, nullptr,
        DC_, DC_, D_, DC_,
        (long)TC_ * DC_, 0, 0, 0, (long)N_ * D_, 0, 1,
        b_kc, cond_mask, (long)TC_, 1);
    hgemm<<<dim3(D_ / 128, TC_ / 128, B_), 256, HG_SMEM_BYTES>>>(
        cnh, cnl, wvch, vb, nullptr, nullptr,
        DC_, DC_, D_, DC_,
        (long)TC_ * DC_, 0, 0, 0, (long)N_ * D_, 0, 1,
        b_vc, cond_mask, (long)TC_, 2);

    // softmax over sequence axis (exp in place + column sums)
    ksoftmax_kernel<<<dim3(D_ / 64, B_), 256>>>(keyb, cs);

    // attn = normalized k^T v (fp32, split-K(10) + atomics)
    zero_kernel<<<(B_ * H_ * HD_ * HD_ + 255) / 256, 256>>>(attnT, B_ * H_ * HD_ * HD_);
    attn_kernel<<<dim3(10, H_, B_), 256>>>(keyb, vb, cs, attnT);

    // attnT -> fp16 (4 MB, tiny; W-side of q@attn needs hi only)
    {
        int n4 = (B_ * H_ * HD_ * HD_) / 4;
        cvt_h<<<(n4 + 255) / 256, 256>>>((const float4*)attnT, (__half2*)ath, n4);
    }

    // y = q @ attn on tensor cores, batched over z = b*H + h; writes fp16 hi/lo directly
    hgemm<<<dim3(1, T_ / 128, B_ * H_), 256, HG_SMEM_BYTES>>>(
        qh, ql, ath, nullptr, yh, yl,
        D_, HD_, D_, HD_,
        (long)T_ * D_, (long)HD_,                 // A: zo=b -> +T*D, zi=h -> +HD
        (long)H_ * HD_ * HD_, (long)HD_ * HD_,    // W: zo=b, zi=h
        (long)T_ * D_, (long)HD_,                 // C: zo=b, zi=h
        H_, nullptr, nullptr, 0, 3);

    // out = y @ W_y^T + b_y on tensor cores
    hgemm<<<dim3(D_ / 128, (B_ * T_) / 128, 1), 256, HG_SMEM_BYTES>>>(
        yh, yl, wyh, out, nullptr, nullptr,
        D_, D_, D_, D_,
        0, 0, 0, 0, 0, 0, 1,
        b_y, nullptr, 0, 0);
}

// round 17
// speedup vs baseline: 2.2606x; 1.1410x over previous
#include <cuda_runtime.h>
#include <cuda_fp16.h>
#include <cstdint>

// ---------------- problem constants ----------------
#define B_   8
#define T_   2048
#define TC_  512
#define D_   1024
#define DC_  512
#define N_   2560   // T_ + TC_
#define H_   8
#define HD_  128
#define NEGV (-1000000.0f)

// ---------------- scratch (device globals: allocation-free rule) ----------------
__device__ float  g_kT[(size_t)B_ * D_ * N_];    // keys transposed [b, d, n] (fp32: holds -1e6 penalties)
__device__ __half g_kexp[(size_t)B_ * D_ * N_];  // exp(k - max) fp16 [b, d, n]
__device__ __half g_vT[(size_t)B_ * D_ * N_];    // values transposed fp16 [b, l, n]
__device__ float  g_colsum[B_ * D_];

__device__ __half g_xn_h[(size_t)B_ * T_ * D_];
__device__ __half g_xn_l[(size_t)B_ * T_ * D_];
__device__ __half g_cn_h[(size_t)B_ * TC_ * DC_];
__device__ __half g_cn_l[(size_t)B_ * TC_ * DC_];
__device__ __half g_q_h[(size_t)B_ * T_ * D_];
__device__ __half g_q_l[(size_t)B_ * T_ * D_];
__device__ __half g_at_h[(size_t)B_ * H_ * HD_ * HD_];
__device__ __half g_y_h[(size_t)B_ * T_ * D_];
__device__ __half g_y_l[(size_t)B_ * T_ * D_];
__device__ __half g_wkx_h[D_ * D_];
__device__ __half g_wvx_h[D_ * D_];
__device__ __half g_wy_h[D_ * D_];
__device__ __half g_wkc_h[D_ * DC_];
__device__ __half g_wvc_h[D_ * DC_];

// ---------------- small PTX helpers (plain sm_103-safe: sm_80-era ISA only) ----------------
__device__ __forceinline__ uint32_t smem_u32(const void* p) {
    uint32_t a;
    asm("{ .reg .u64 t; cvta.to.shared.u64 t, %1; cvt.u32.u64 %0, t; }" : "=r"(a) : "l"(p));
    return a;
}
#define CP_ASYNC16(sm, gp) \
    asm volatile("cp.async.cg.shared.global [%0], [%1], 16;" :: "r"(sm), "l"(gp) : "memory")
#define CP_COMMIT() asm volatile("cp.async.commit_group;" ::: "memory")
#define CP_WAIT(n)  asm volatile("cp.async.wait_group %0;" :: "n"(n) : "memory")

__device__ __forceinline__ void ldmatrix4(uint32_t* r, uint32_t addr) {
    asm volatile("ldmatrix.sync.aligned.m8n8.x4.shared.b16 {%0,%1,%2,%3}, [%4];"
                 : "=r"(r[0]), "=r"(r[1]), "=r"(r[2]), "=r"(r[3]) : "r"(addr));
}
__device__ __forceinline__ void mma16816(float* d, const uint32_t* a, uint32_t b0, uint32_t b1) {
    asm volatile("mma.sync.aligned.m16n8k16.row.col.f32.f16.f16.f32 "
                 "{%0,%1,%2,%3}, {%4,%5,%6,%7}, {%8,%9}, {%0,%1,%2,%3};"
                 : "+f"(d[0]), "+f"(d[1]), "+f"(d[2]), "+f"(d[3])
                 : "r"(a[0]), "r"(a[1]), "r"(a[2]), "r"(a[3]), "r"(b0), "r"(b1));
}

// ---------------- fp16 split HMMA GEMM ----------------
//  C = (Ah [+ Al])(M,K) * Wh(N,K)^T  (fp32 accum); nsplit = 1 or 2 K-passes.
//  CTA tile 128x128, warp tile 64x32, K-chunk 64, 3-stage cp.async multistage
//  (mainloop identical to the validated R11/R15 kernel).
//  Batch: z -> zo = z / zInner, zi = z % zInner; offsets aO*zo + aI*zi etc.
//  epilogue modes:
//    0: fp32 +bias                      1: fp32 +bias + (1-mask[m])*NEG
//    3: fp16 hi/lo pair to Chi/Clo      4: TRANSPOSED fp16 (bias then *mask[m]) to Chi
//    5: TRANSPOSED fp32 (bias + (1-mask[m])*NEG) to C
//    6: fp16 to Chi, column-scaled by 1/bias[col] (bias offset by biasO/biasI per z)
#define HG_STAGES      3
#define HG_STAGE_BYTES 32768          // A 16KB + B 16KB
#define HG_SMEM_BYTES  (1024 + HG_STAGES * HG_STAGE_BYTES)

__device__ __forceinline__ void hg_issue_chunk(
    const __half* Ap, const __half* Wp,
    int m0, int n0, int lda, int ldw, int k0,
    uint32_t sA, uint32_t sB, int tid)
{
#pragma unroll
    for (int i = 0; i < 4; ++i) {
        const int u = tid + i * 256;
        const int row = u >> 3, kg = u & 7;
        const uint32_t sw = row * 128 + (((uint32_t)(kg ^ (row & 7))) << 4);
        CP_ASYNC16(sA + sw, Ap + (size_t)(m0 + row) * lda + k0 + kg * 8);
    }
#pragma unroll
    for (int i = 0; i < 4; ++i) {
        const int u = tid + i * 256;
        const int row = u >> 3, kg = u & 7;
        const uint32_t sw = row * 128 + (((uint32_t)(kg ^ (row & 7))) << 4);
        CP_ASYNC16(sB + sw, Wp + (size_t)(n0 + row) * ldw + k0 + kg * 8);
    }
    CP_COMMIT();
}

__global__ void __launch_bounds__(256, 2) hgemm(
    const __half* __restrict__ Ah, const __half* __restrict__ Al,
    const __half* __restrict__ Wh,
    float* __restrict__ C,
    __half* __restrict__ Chi, __half* __restrict__ Clo,
    int lda, int ldw, int ldc, int Kd,
    long aO, long aI, long wO, long wI, long cO, long cI, int zInner, int nsplit,
    const float* __restrict__ bias, long biasO, long biasI,
    const float* __restrict__ mask, long maskStride, int mode)
{
    extern __shared__ char smraw[];
    const uint32_t sbase = (smem_u32(smraw) + 1023u) & ~1023u;

    const int tid = threadIdx.x;
    const int w = tid >> 5, lane = tid & 31;
    const long z = blockIdx.z;
    const long zo = z / zInner, zi = z % zInner;
    const long aoff = zo * aO + zi * aI;
    const long woff = zo * wO + zi * wI;
    const long coff = zo * cO + zi * cI;
    Ah += aoff; if (Al) Al += aoff;
    Wh += woff;
    if (C)   C   += coff;
    if (Chi) Chi += coff;
    if (Clo) Clo += coff;
    if (bias) bias += zo * biasO + zi * biasI;
    const float* mk = mask ? (mask + zo * maskStride) : nullptr;
    const int m0 = blockIdx.y * 128, n0 = blockIdx.x * 128;

    const int wm = (w >> 2) * 64;     // warp row base within tile (0 or 64)
    const int wn = (w & 3) * 32;      // warp col base within tile

    float acc[4][4][4];
#pragma unroll
    for (int a = 0; a < 4; ++a)
#pragma unroll
        for (int b = 0; b < 4; ++b)
#pragma unroll
            for (int c = 0; c < 4; ++c) acc[a][b][c] = 0.f;

    const int kc = Kd >> 6;           // K-chunks per pass
    const int nchunks = nsplit * kc;

    auto srcA = [&](int phase) { return phase ? Al : Ah; };

    // prologue: issue chunks 0 and 1 into slots 0, 1 (slot 2 stays free)
    {
        hg_issue_chunk(srcA(0), Wh, m0, n0, lda, ldw, 0,
                       sbase, sbase + 16384, tid);
        const int p1 = 1 / kc;
        const int k1 = (1 - p1 * kc) << 6;
        hg_issue_chunk(srcA(p1), Wh, m0, n0, lda, ldw, k1,
                       sbase + HG_STAGE_BYTES, sbase + HG_STAGE_BYTES + 16384, tid);
    }

    const int rl = lane & 15;         // row within 16-row group
    const int kh = lane >> 4;         // 0/1 -> k-subgroup select

    for (int c = 0; c < nchunks; ++c) {
        CP_WAIT(1);
        __syncthreads();

        if (c + 2 < nchunks) {
            const int cn = c + 2;
            const int ph = cn / kc;
            const int k0 = (cn - ph * kc) << 6;
            const uint32_t slot = sbase + (uint32_t)(cn % HG_STAGES) * HG_STAGE_BYTES;
            hg_issue_chunk(srcA(ph), Wh, m0, n0, lda, ldw, k0,
                           slot, slot + 16384, tid);
        } else {
            CP_COMMIT();
        }

        const uint32_t sA = sbase + (uint32_t)(c % HG_STAGES) * HG_STAGE_BYTES;
        const uint32_t sB = sA + 16384;

#pragma unroll
        for (int ks = 0; ks < 4; ++ks) {
            const int kg = 2 * ks + kh;
            uint32_t ar[4][4];
#pragma unroll
            for (int tm = 0; tm < 4; ++tm) {
                const int row = wm + tm * 16 + rl;
                ldmatrix4(ar[tm], sA + row * 128 + (((uint32_t)(kg ^ (row & 7))) << 4));
            }
            uint32_t br[2][4];
#pragma unroll
            for (int tp = 0; tp < 2; ++tp) {
                const int row = wn + tp * 16 + rl;
                ldmatrix4(br[tp], sB + row * 128 + (((uint32_t)(kg ^ (row & 7))) << 4));
            }
#pragma unroll
            for (int tm = 0; tm < 4; ++tm)
#pragma unroll
                for (int tn = 0; tn < 4; ++tn) {
                    const uint32_t* bb = br[tn >> 1];
                    const int u = tn & 1;
                    mma16816(acc[tm][tn], ar[tm], bb[u], bb[u + 2]);
                }
        }
    }

    // ---------------- epilogue ----------------
    const int r0l = lane >> 2;        // 0..7
    const int c0l = (lane & 3) * 2;

    if (mode == 4 || mode == 5) {
        // transposed output via smem staging (stages are free after the mainloop)
        __syncthreads();
        if (mode == 5) {
            float* st = reinterpret_cast<float*>(smraw);   // pitch 136 floats
#pragma unroll
            for (int tm = 0; tm < 4; ++tm) {
                const int rr = wm + tm * 16 + r0l;
                const float p0 = (1.f - mk[m0 + rr]) * NEGV;
                const float p1 = (1.f - mk[m0 + rr + 8]) * NEGV;
#pragma unroll
                for (int tn = 0; tn < 4; ++tn) {
                    const int cc = wn + tn * 8 + c0l;
                    const float b0 = bias[n0 + cc], b1 = bias[n0 + cc + 1];
                    st[(cc)     * 136 + rr]     = acc[tm][tn][0] + b0 + p0;
                    st[(cc + 1) * 136 + rr]     = acc[tm][tn][1] + b1 + p0;
                    st[(cc)     * 136 + rr + 8] = acc[tm][tn][2] + b0 + p1;
                    st[(cc + 1) * 136 + rr + 8] = acc[tm][tn][3] + b1 + p1;
                }
            }
            __syncthreads();
            const int cc2 = tid >> 1, rr2 = (tid & 1) * 64;
            float* dst = C + (size_t)(n0 + cc2) * ldc + (m0 + rr2);
            const float* srcp = st + cc2 * 136 + rr2;
#pragma unroll
            for (int j = 0; j < 64; j += 4)
                *(float4*)(dst + j) = *(const float4*)(srcp + j);
        } else {
            __half* st = reinterpret_cast<__half*>(smraw); // pitch 136 halfs
#pragma unroll
            for (int tm = 0; tm < 4; ++tm) {
                const int rr = wm + tm * 16 + r0l;
                const float mk0 = mk[m0 + rr];
                const float mk1 = mk[m0 + rr + 8];
#pragma unroll
                for (int tn = 0; tn < 4; ++tn) {
                    const int cc = wn + tn * 8 + c0l;
                    const float b0 = bias[n0 + cc], b1 = bias[n0 + cc + 1];
                    st[(cc)     * 136 + rr]     = __float2half((acc[tm][tn][0] + b0) * mk0);
                    st[(cc + 1) * 136 + rr]     = __float2half((acc[tm][tn][1] + b1) * mk0);
                    st[(cc)     * 136 + rr + 8] = __float2half((acc[tm][tn][2] + b0) * mk1);
                    st[(cc + 1) * 136 + rr + 8] = __float2half((acc[tm][tn][3] + b1) * mk1);
                }
            }
            __syncthreads();
            const int cc2 = tid >> 1, rr2 = (tid & 1) * 64;
            __half* dst = Chi + (size_t)(n0 + cc2) * ldc + (m0 + rr2);
            const __half* srcp = st + cc2 * 136 + rr2;
#pragma unroll
            for (int j = 0; j < 64; j += 8)
                *(uint4*)(dst + j) = *(const uint4*)(srcp + j);
        }
        return;
    }
    if (mode == 6) {
        // fp16 out, column-scaled by 1/bias[col]
#pragma unroll
        for (int tm = 0; tm < 4; ++tm) {
            const int row0 = m0 + wm + tm * 16 + r0l;
            const int row1 = row0 + 8;
            __half* h0 = Chi + (size_t)row0 * ldc;
            __half* h1 = Chi + (size_t)row1 * ldc;
#pragma unroll
            for (int tn = 0; tn < 4; ++tn) {
                const int col = n0 + wn + tn * 8 + c0l;
                const float i0 = 1.0f / bias[col], i1 = 1.0f / bias[col + 1];
                *(__half2*)(h0 + col) = __halves2half2(
                    __float2half(acc[tm][tn][0] * i0), __float2half(acc[tm][tn][1] * i1));
                *(__half2*)(h1 + col) = __halves2half2(
                    __float2half(acc[tm][tn][2] * i0), __float2half(acc[tm][tn][3] * i1));
            }
        }
        return;
    }
    if (mode == 3) {
        // fp16 hi/lo pair
#pragma unroll
        for (int tm = 0; tm < 4; ++tm) {
            const int row0 = m0 + wm + tm * 16 + r0l;
            const int row1 = row0 + 8;
            __half* h0 = Chi + (size_t)row0 * ldc;
            __half* h1 = Chi + (size_t)row1 * ldc;
            __half* l0 = Clo + (size_t)row0 * ldc;
            __half* l1 = Clo + (size_t)row1 * ldc;
#pragma unroll
            for (int tn = 0; tn < 4; ++tn) {
                const int col = n0 + wn + tn * 8 + c0l;
                const float d0 = acc[tm][tn][0], d1 = acc[tm][tn][1];
                const float d2 = acc[tm][tn][2], d3 = acc[tm][tn][3];
                __half a0 = __float2half(d0), a1 = __float2half(d1);
                __half a2 = __float2half(d2), a3 = __float2half(d3);
                *(__half2*)(h0 + col) = __halves2half2(a0, a1);
                *(__half2*)(h1 + col) = __halves2half2(a2, a3);
                *(__half2*)(l0 + col) = __halves2half2(
                    __float2half(d0 - __half2float(a0)),
                    __float2half(d1 - __half2float(a1)));
                *(__half2*)(l1 + col) = __halves2half2(
                    __float2half(d2 - __half2float(a2)),
                    __float2half(d3 - __half2float(a3)));
            }
        }
        return;
    }
    // modes 0 / 1: fp32 output
#pragma unroll
    for (int tm = 0; tm < 4; ++tm) {
        const int row0 = m0 + wm + tm * 16 + r0l;
        const int row1 = row0 + 8;
        float mk0 = 0.f, mk1 = 0.f;
        if (mk) { mk0 = mk[row0]; mk1 = mk[row1]; }
        float* cr0 = C + (size_t)row0 * ldc;
        float* cr1 = C + (size_t)row1 * ldc;
#pragma unroll
        for (int tn = 0; tn < 4; ++tn) {
            const int col = n0 + wn + tn * 8 + c0l;
            float d0 = acc[tm][tn][0], d1 = acc[tm][tn][1];
            float d2 = acc[tm][tn][2], d3 = acc[tm][tn][3];
            if (bias) {
                const float b0 = bias[col], b1 = bias[col + 1];
                d0 += b0; d1 += b1; d2 += b0; d3 += b1;
            }
            if (mode == 1) {
                const float p0 = (1.f - mk0) * NEGV, p1 = (1.f - mk1) * NEGV;
                d0 += p0; d1 += p0; d2 += p1; d3 += p1;
            }
            float2 s0; s0.x = d0; s0.y = d1;
            float2 s1; s1.x = d2; s1.y = d3;
            *(float2*)(cr0 + col) = s0;
            *(float2*)(cr1 + col) = s1;
        }
    }
}

// ---------------- layernorm -> fp16 hi/lo ----------------
template <int DLEN>
__global__ void __launch_bounds__(256) ln_hilo(const float* __restrict__ x,
                                               const float* __restrict__ gam,
                                               const float* __restrict__ bet,
                                               __half* __restrict__ hi,
                                               __half* __restrict__ lo)
{
    constexpr int PER = DLEN / 256;
    const size_t row = blockIdx.x;
    const float* xr = x + row * DLEN;
    float v[PER];
    float s = 0.f, sq = 0.f;
#pragma unroll
    for (int i = 0; i < PER; i++) {
        v[i] = xr[threadIdx.x + i * 256];
        s += v[i]; sq += v[i] * v[i];
    }
#pragma unroll
    for (int o = 16; o > 0; o >>= 1) {
        s  += __shfl_xor_sync(0xffffffffu, s, o);
        sq += __shfl_xor_sync(0xffffffffu, sq, o);
    }
    __shared__ float rs[8], rq[8];
    int w = threadIdx.x >> 5, l = threadIdx.x & 31;
    if (l == 0) { rs[w] = s; rq[w] = sq; }
    __syncthreads();
    float ts = 0.f, tq = 0.f;
#pragma unroll
    for (int i = 0; i < 8; i++) { ts += rs[i]; tq += rq[i]; }
    const float mean = ts / (float)DLEN;
    const float var = tq / (float)DLEN - mean * mean;
    const float rstd = rsqrtf(var + 1e-5f);
#pragma unroll
    for (int i = 0; i < PER; i++) {
        int c = threadIdx.x + i * 256;
        float o = (v[i] - mean) * rstd * gam[c] + bet[c];
        __half h = __float2half(o);
        hi[row * DLEN + c] = h;
        lo[row * DLEN + c] = __float2half(o - __half2float(h));
    }
}

// ---------------- fp32 -> fp16 convert (weights) ----------------
__global__ void __launch_bounds__(256) cvt_h(const float4* __restrict__ s,
                                             __half2* __restrict__ hi, int n4)
{
    int i = blockIdx.x * blockDim.x + threadIdx.x;
    if (i < n4) {
        float4 v = s[i];
        hi[2 * i]     = __halves2half2(__float2half(v.x), __float2half(v.y));
        hi[2 * i + 1] = __halves2half2(__float2half(v.z), __float2half(v.w));
    }
}

// ---------------- q softmax over last dim (128) -> fp16 hi/lo ----------------
__global__ void __launch_bounds__(256) qsoftmax_kernel(const float* __restrict__ query,
                                                       __half* __restrict__ qh,
                                                       __half* __restrict__ ql)
{
    const size_t row = blockIdx.x;
    int w = threadIdx.x >> 5, l = threadIdx.x & 31;
    const float* src = query + row * D_ + (size_t)w * HD_;
    float4 v = *(const float4*)&src[l * 4];
    float m = fmaxf(fmaxf(v.x, v.y), fmaxf(v.z, v.w));
#pragma unroll
    for (int o = 16; o > 0; o >>= 1) m = fmaxf(m, __shfl_xor_sync(0xffffffffu, m, o));
    float e0 = expf(v.x - m), e1 = expf(v.y - m), e2 = expf(v.z - m), e3 = expf(v.w - m);
    float s = e0 + e1 + e2 + e3;
#pragma unroll
    for (int o = 16; o > 0; o >>= 1) s += __shfl_xor_sync(0xffffffffu, s, o);
    float inv = 1.0f / s;
    float q0 = e0 * inv, q1 = e1 * inv, q2 = e2 * inv, q3 = e3 * inv;
    __half h0 = __float2half(q0), h1 = __float2half(q1);
    __half h2 = __float2half(q2), h3 = __float2half(q3);
    const size_t off = row * D_ + (size_t)w * HD_ + l * 4;
    *(__half2*)(qh + off)     = __halves2half2(h0, h1);
    *(__half2*)(qh + off + 2) = __halves2half2(h2, h3);
    *(__half2*)(ql + off)     = __halves2half2(
        __float2half(q0 - __half2float(h0)),
        __float2half(q1 - __half2float(h1)));
    *(__half2*)(ql + off + 2) = __halves2half2(
        __float2half(q2 - __half2float(h2)),
        __float2half(q3 - __half2float(h3)));
}

// ---------------- key softmax over n (row-wise on transposed kT) ----------------
// one block per (b*D + d) row; reads fp32 kT row (contiguous n), writes fp16 exp + fp32 colsum
__global__ void __launch_bounds__(256) ksoftmax_t(const float* __restrict__ kT,
                                                  __half* __restrict__ kexp,
                                                  float* __restrict__ colsum)
{
    constexpr int PER = N_ / 256;     // 10
    const size_t row = blockIdx.x;
    const float* src = kT + row * N_;
    __half* dst = kexp + row * N_;
    const int tid = threadIdx.x;
    float v[PER];
    float m = -3.0e38f;
#pragma unroll
    for (int i = 0; i < PER; i++) {
        v[i] = src[tid + i * 256];
        m = fmaxf(m, v[i]);
    }
#pragma unroll
    for (int o = 16; o > 0; o >>= 1) m = fmaxf(m, __shfl_xor_sync(0xffffffffu, m, o));
    __shared__ float red[8];
    int w = tid >> 5, l = tid & 31;
    if (l == 0) red[w] = m;
    __syncthreads();
#pragma unroll
    for (int i = 0; i < 8; i++) m = fmaxf(m, red[i]);
    __syncthreads();
    float s = 0.f;
#pragma unroll
    for (int i = 0; i < PER; i++) {
        float e = expf(v[i] - m);
        v[i] = e;
        s += e;
    }
#pragma unroll
    for (int o = 16; o > 0; o >>= 1) s += __shfl_xor_sync(0xffffffffu, s, o);
    if (l == 0) red[w] = s;
    __syncthreads();
    float tot = 0.f;
#pragma unroll
    for (int i = 0; i < 8; i++) tot += red[i];
#pragma unroll
    for (int i = 0; i < PER; i++)
        dst[tid + i * 256] = __float2half(v[i]);
    if (tid == 0) colsum[row] = tot;
}

// ---------------- host launch ----------------
extern "C" void kernel_launch(void* const* d_in, const int* in_sizes, int n_in,
                              void* d_out, int out_size)
{
    const float* query     = (const float*)d_in[0];
    const float* x         = (const float*)d_in[1];
    const float* cond_emb  = (const float*)d_in[2];
    const float* src_mask  = (const float*)d_in[3];
    const float* cond_mask = (const float*)d_in[4];
    const float* nxg = (const float*)d_in[5];
    const float* nxb = (const float*)d_in[6];
    const float* ncg = (const float*)d_in[7];
    const float* ncb = (const float*)d_in[8];
    const float* W_kc = (const float*)d_in[9];
    const float* b_kc = (const float*)d_in[10];
    const float* W_vc = (const float*)d_in[11];
    const float* b_vc = (const float*)d_in[12];
    const float* W_kx = (const float*)d_in[13];
    const float* b_kx = (const float*)d_in[14];
    const float* W_vx = (const float*)d_in[15];
    const float* b_vx = (const float*)d_in[16];
    const float* W_y  = (const float*)d_in[17];
    const float* b_y  = (const float*)d_in[18];
    float* out = (float*)d_out;

    float *kT, *cs;
    __half *kexp, *vT;
    __half *xnh, *xnl, *cnh, *cnl, *qh, *ql, *ath, *yh, *yl;
    __half *wkxh, *wvxh, *wyh, *wkch, *wvch;
    cudaGetSymbolAddress((void**)&kT, g_kT);
    cudaGetSymbolAddress((void**)&kexp, g_kexp);
    cudaGetSymbolAddress((void**)&vT, g_vT);
    cudaGetSymbolAddress((void**)&cs, g_colsum);
    cudaGetSymbolAddress((void**)&xnh, g_xn_h); cudaGetSymbolAddress((void**)&xnl, g_xn_l);
    cudaGetSymbolAddress((void**)&cnh, g_cn_h); cudaGetSymbolAddress((void**)&cnl, g_cn_l);
    cudaGetSymbolAddress((void**)&qh, g_q_h);   cudaGetSymbolAddress((void**)&ql, g_q_l);
    cudaGetSymbolAddress((void**)&ath, g_at_h);
    cudaGetSymbolAddress((void**)&yh, g_y_h);   cudaGetSymbolAddress((void**)&yl, g_y_l);
    cudaGetSymbolAddress((void**)&wkxh, g_wkx_h);
    cudaGetSymbolAddress((void**)&wvxh, g_wvx_h);
    cudaGetSymbolAddress((void**)&wyh, g_wy_h);
    cudaGetSymbolAddress((void**)&wkch, g_wkc_h);
    cudaGetSymbolAddress((void**)&wvch, g_wvc_h);

    cudaFuncSetAttribute(hgemm, cudaFuncAttributeMaxDynamicSharedMemorySize, HG_SMEM_BYTES);

    // elementwise prep
    ln_hilo<D_><<<B_ * T_, 256>>>(x, nxg, nxb, xnh, xnl);
    ln_hilo<DC_><<<B_ * TC_, 256>>>(cond_emb, ncg, ncb, cnh, cnl);
    qsoftmax_kernel<<<B_ * T_, 256>>>(query, qh, ql);
    {
        int n4 = (D_ * D_) / 4;
        cvt_h<<<(n4 + 255) / 256, 256>>>((const float4*)W_kx, (__half2*)wkxh, n4);
        cvt_h<<<(n4 + 255) / 256, 256>>>((const float4*)W_vx, (__half2*)wvxh, n4);
        cvt_h<<<(n4 + 255) / 256, 256>>>((const float4*)W_y,  (__half2*)wyh,  n4);
        int n4c = (D_ * DC_) / 4;
        cvt_h<<<(n4c + 255) / 256, 256>>>((const float4*)W_kc, (__half2*)wkch, n4c);
        cvt_h<<<(n4c + 255) / 256, 256>>>((const float4*)W_vc, (__half2*)wvch, n4c);
    }

    // k/v projections -> TRANSPOSED outputs (kT fp32 mode 5, vT fp16 mode 4)
    // x tokens land at n in [TC_, N_), cond tokens at [0, TC_)  (pointer offset)
    hgemm<<<dim3(D_ / 128, T_ / 128, B_), 256, HG_SMEM_BYTES>>>(
        xnh, xnl, wkxh, kT + TC_, nullptr, nullptr,
        D_, D_, N_, D_,
        (long)T_ * D_, 0, 0, 0, (long)D_ * N_, 0, 1, 2,
        b_kx, 0, 0, src_mask, (long)T_, 5);
    hgemm<<<dim3(D_ / 128, T_ / 128, B_), 256, HG_SMEM_BYTES>>>(
        xnh, xnl, wvxh, nullptr, vT + TC_, nullptr,
        D_, D_, N_, D_,
        (long)T_ * D_, 0, 0, 0, (long)D_ * N_, 0, 1, 2,
        b_vx, 0, 0, src_mask, (long)T_, 4);
    hgemm<<<dim3(D_ / 128, TC_ / 128, B_), 256, HG_SMEM_BYTES>>>(
        cnh, cnl, wkch, kT, nullptr, nullptr,
        DC_, DC_, N_, DC_,
        (long)TC_ * DC_, 0, 0, 0, (long)D_ * N_, 0, 1, 2,
        b_kc, 0, 0, cond_mask, (long)TC_, 5);
    hgemm<<<dim3(D_ / 128, TC_ / 128, B_), 256, HG_SMEM_BYTES>>>(
        cnh, cnl, wvch, nullptr, vT, nullptr,
        DC_, DC_, N_, DC_,
        (long)TC_ * DC_, 0, 0, 0, (long)D_ * N_, 0, 1, 2,
        b_vc, 0, 0, cond_mask, (long)TC_, 4);

    // softmax over sequence axis: row-wise on kT, emits fp16 exp + fp32 colsum
    ksoftmax_t<<<B_ * D_, 256>>>(kT, kexp, cs);

    // attn on tensor cores: ath[l,d] = (1/colsum[d]) * sum_n vT[l,n] * kexp[d,n]
    hgemm<<<dim3(1, 1, B_ * H_), 256, HG_SMEM_BYTES>>>(
        vT, nullptr, kexp, nullptr, ath, nullptr,
        N_, N_, HD_, N_,
        (long)D_ * N_, (long)HD_ * N_,            // A: zo=b, zi=h
        (long)D_ * N_, (long)HD_ * N_,            // W: zo=b, zi=h
        (long)H_ * HD_ * HD_, (long)HD_ * HD_,    // C: zo=b, zi=h
        H_, 1,
        cs, (long)D_, (long)HD_,                  // colsum[b*D + h*128 + col]
        nullptr, 0, 6);

    // y = q @ attn on tensor cores, batched over z = b*H + h; writes fp16 hi/lo
    hgemm<<<dim3(1, T_ / 128, B_ * H_), 256, HG_SMEM_BYTES>>>(
        qh, ql, ath, nullptr, yh, yl,
        D_, HD_, D_, HD_,
        (long)T_ * D_, (long)HD_,
        (long)H_ * HD_ * HD_, (long)HD_ * HD_,
        (long)T_ * D_, (long)HD_,
        H_, 2, nullptr, 0, 0, nullptr, 0, 3);

    // out = y @ W_y^T + b_y on tensor cores
    hgemm<<<dim3(D_ / 128, (B_ * T_) / 128, 1), 256, HG_SMEM_BYTES>>>(
        yh, yl, wyh, out, nullptr, nullptr,
        D_, D_, D_, D_,
        0, 0, 0, 0, 0, 0, 1, 2,
        b_y, 0, 0, nullptr, 0, 0);
}